// round 1
// baseline (speedup 1.0000x reference)
#include <cuda_runtime.h>
#include <math.h>

// Problem dims
#define BB   16
#define LL   1024
#define DD   1024
#define HH   8
#define KHD  128      // head dim
#define OUTN 64

// -------- scratch (device globals; no allocations allowed) --------
__device__ float g_q  [BB * LL * DD];           // 64 MB
__device__ float g_k  [BB * LL * DD];           // 64 MB
__device__ float g_v  [BB * LL * DD];           // 64 MB
__device__ float g_sc [(long)BB * HH * LL * LL];// 512 MB scores
__device__ float g_att[BB * LL * DD];           // 64 MB
__device__ float g_uni[BB * LL * DD];           // 64 MB
__device__ float g_pool[BB * DD];

// =================================================================
// GEMM TN: C[m,n] = alpha * sum_k A[m,k] * B[n,k]  (+ bias[n])
// A row-major [M,Kd] lda, B row-major [N,Kd] ldb (i.e. x @ W^T).
// Batched via blockIdx.z: off = (z/hdiv)*s1 + (z%hdiv)*s2 per tensor.
// BM=BN=64, BK=16, 256 threads, 4x4 micro-tile per thread.
// =================================================================
__global__ void gemm_tn(const float* __restrict__ A, int lda, long sA1, long sA2,
                        const float* __restrict__ B, int ldb, long sB1, long sB2,
                        float* __restrict__ C, int ldc, long sC1, long sC2,
                        int Kd, float alpha, const float* __restrict__ bias,
                        int hdiv)
{
    const int z  = blockIdx.z;
    const int zb = z / hdiv, zh = z % hdiv;
    A += (long)zb * sA1 + (long)zh * sA2;
    B += (long)zb * sB1 + (long)zh * sB2;
    C += (long)zb * sC1 + (long)zh * sC2;

    __shared__ float As[16][68];
    __shared__ float Bs[16][68];

    const int tid = threadIdx.x;
    const int tx = tid & 15, ty = tid >> 4;
    const int bm = blockIdx.y * 64, bn = blockIdx.x * 64;

    float acc[4][4] = {};
    const int lr = tid >> 4;   // 0..15
    const int lc = tid & 15;   // 0..15

    for (int k0 = 0; k0 < Kd; k0 += 16) {
        #pragma unroll
        for (int i = 0; i < 4; ++i) {
            int r = lr + 16 * i;
            As[lc][r] = A[(long)(bm + r) * lda + k0 + lc];
            Bs[lc][r] = B[(long)(bn + r) * ldb + k0 + lc];
        }
        __syncthreads();
        #pragma unroll
        for (int k = 0; k < 16; ++k) {
            float a[4], b[4];
            #pragma unroll
            for (int j = 0; j < 4; ++j) a[j] = As[k][ty * 4 + j];
            #pragma unroll
            for (int j = 0; j < 4; ++j) b[j] = Bs[k][tx * 4 + j];
            #pragma unroll
            for (int i = 0; i < 4; ++i)
                #pragma unroll
                for (int j = 0; j < 4; ++j) acc[i][j] += a[i] * b[j];
        }
        __syncthreads();
    }

    #pragma unroll
    for (int i = 0; i < 4; ++i) {
        const int m = bm + ty * 4 + i;
        #pragma unroll
        for (int j = 0; j < 4; ++j) {
            const int n = bn + tx * 4 + j;
            float vv = acc[i][j] * alpha;
            if (bias) vv += bias[n];
            C[(long)m * ldc + n] = vv;
        }
    }
}

// =================================================================
// GEMM NN: C[m,n] = sum_k A[m,k] * B[k,n]   (attn @ V)
// A row-major [M,Kd] lda; B row-major [Kd,N] ldb.
// =================================================================
__global__ void gemm_nn(const float* __restrict__ A, int lda, long sA1, long sA2,
                        const float* __restrict__ B, int ldb, long sB1, long sB2,
                        float* __restrict__ C, int ldc, long sC1, long sC2,
                        int Kd, int hdiv)
{
    const int z  = blockIdx.z;
    const int zb = z / hdiv, zh = z % hdiv;
    A += (long)zb * sA1 + (long)zh * sA2;
    B += (long)zb * sB1 + (long)zh * sB2;
    C += (long)zb * sC1 + (long)zh * sC2;

    __shared__ float As[16][68];
    __shared__ float Bs[16][68];

    const int tid = threadIdx.x;
    const int tx = tid & 15, ty = tid >> 4;
    const int bm = blockIdx.y * 64, bn = blockIdx.x * 64;

    float acc[4][4] = {};
    const int lrA = tid >> 4, lcA = tid & 15;     // A tile loader: 16x16 threads
    const int lrB = tid >> 6, lcB = tid & 63;     // B tile loader: 4 rows x 64 cols

    for (int k0 = 0; k0 < Kd; k0 += 16) {
        #pragma unroll
        for (int i = 0; i < 4; ++i) {
            int r = lrA + 16 * i;
            As[lcA][r] = A[(long)(bm + r) * lda + k0 + lcA];
        }
        #pragma unroll
        for (int i = 0; i < 4; ++i) {
            int kk = lrB + 4 * i;
            Bs[kk][lcB] = B[(long)(k0 + kk) * ldb + bn + lcB];
        }
        __syncthreads();
        #pragma unroll
        for (int k = 0; k < 16; ++k) {
            float a[4], b[4];
            #pragma unroll
            for (int j = 0; j < 4; ++j) a[j] = As[k][ty * 4 + j];
            #pragma unroll
            for (int j = 0; j < 4; ++j) b[j] = Bs[k][tx * 4 + j];
            #pragma unroll
            for (int i = 0; i < 4; ++i)
                #pragma unroll
                for (int j = 0; j < 4; ++j) acc[i][j] += a[i] * b[j];
        }
        __syncthreads();
    }

    #pragma unroll
    for (int i = 0; i < 4; ++i) {
        const int m = bm + ty * 4 + i;
        #pragma unroll
        for (int j = 0; j < 4; ++j) {
            const int n = bn + tx * 4 + j;
            C[(long)m * ldc + n] = acc[i][j];
        }
    }
}

// =================================================================
// Row softmax over last dim (n = LL), one block per row.
// =================================================================
__global__ void softmax_rows(float* __restrict__ sc)
{
    float* p = sc + (long)blockIdx.x * LL;
    const int t = threadIdx.x;                       // 256 threads
    __shared__ float red[8];

    float mx = -1e30f;
    #pragma unroll
    for (int i = t; i < LL; i += 256) mx = fmaxf(mx, p[i]);
    #pragma unroll
    for (int o = 16; o; o >>= 1) mx = fmaxf(mx, __shfl_xor_sync(~0u, mx, o));
    if ((t & 31) == 0) red[t >> 5] = mx;
    __syncthreads();
    if (t < 32) {
        float v = (t < 8) ? red[t] : -1e30f;
        #pragma unroll
        for (int o = 4; o; o >>= 1) v = fmaxf(v, __shfl_xor_sync(~0u, v, o));
        if (t == 0) red[0] = v;
    }
    __syncthreads();
    mx = red[0];
    __syncthreads();

    float s = 0.f;
    #pragma unroll
    for (int i = t; i < LL; i += 256) {
        float e = __expf(p[i] - mx);
        p[i] = e;
        s += e;
    }
    #pragma unroll
    for (int o = 16; o; o >>= 1) s += __shfl_xor_sync(~0u, s, o);
    if ((t & 31) == 0) red[t >> 5] = s;
    __syncthreads();
    if (t < 32) {
        float v = (t < 8) ? red[t] : 0.f;
        #pragma unroll
        for (int o = 4; o; o >>= 1) v += __shfl_xor_sync(~0u, v, o);
        if (t == 0) red[0] = v;
    }
    __syncthreads();
    const float inv = 1.f / red[0];
    for (int i = t; i < LL; i += 256) p[i] *= inv;
}

// =================================================================
// Pool: pooled[b,n] = mean_l uni[b,l,n] + max_l uni[b,l,n]
// grid (DD/256, BB), 256 threads
// =================================================================
__global__ void pool_kernel(const float* __restrict__ uni, float* __restrict__ pool)
{
    const int n = blockIdx.x * 256 + threadIdx.x;
    const int b = blockIdx.y;
    const float* p = uni + (long)b * LL * DD + n;
    float s = 0.f, m = -1e30f;
    for (int l = 0; l < LL; ++l) {
        float v = p[(long)l * DD];
        s += v;
        m = fmaxf(m, v);
    }
    pool[b * DD + n] = s * (1.f / LL) + m;
}

// =================================================================
// Logits: out[b,o] = pooled[b,:] . Wmlp[o,:] + bmlp[o]
// grid BB, 256 threads (only o<64 compute)
// =================================================================
__global__ void logits_kernel(const float* __restrict__ pool,
                              const float* __restrict__ Wm,
                              const float* __restrict__ bm,
                              float* __restrict__ out)
{
    const int b = blockIdx.x;
    __shared__ float ps[DD];
    for (int i = threadIdx.x; i < DD; i += blockDim.x) ps[i] = pool[b * DD + i];
    __syncthreads();
    const int o = threadIdx.x;
    if (o < OUTN) {
        float s = bm[o];
        const float* w = Wm + (long)o * DD;
        for (int kk = 0; kk < DD; ++kk) s += ps[kk] * w[kk];
        out[b * OUTN + o] = s;
    }
}

// =================================================================
extern "C" void kernel_launch(void* const* d_in, const int* in_sizes, int n_in,
                              void* d_out, int out_size)
{
    const float* x0   = (const float*)d_in[0];
    const float* x1   = (const float*)d_in[1];
    const float* x2   = (const float*)d_in[2];
    // d_in[3] support, d_in[4] mask: unused by reference
    const float* Wk   = (const float*)d_in[5];
    const float* Wq   = (const float*)d_in[6];
    const float* Wv   = (const float*)d_in[7];
    const float* Wu   = (const float*)d_in[8];
    const float* bu   = (const float*)d_in[9];
    const float* Wmlp = (const float*)d_in[10];
    const float* bmlp = (const float*)d_in[11];
    float* out = (float*)d_out;

    float *q, *k, *v, *sc, *att, *uni, *pool;
    cudaGetSymbolAddress((void**)&q,   g_q);
    cudaGetSymbolAddress((void**)&k,   g_k);
    cudaGetSymbolAddress((void**)&v,   g_v);
    cudaGetSymbolAddress((void**)&sc,  g_sc);
    cudaGetSymbolAddress((void**)&att, g_att);
    cudaGetSymbolAddress((void**)&uni, g_uni);
    cudaGetSymbolAddress((void**)&pool, g_pool);

    const float scale = powf((float)KHD, -0.25f);
    const int M  = BB * LL;     // 16384
    dim3 blk(256);

    // --- QKV projections: [16384,1024] @ [1024,1024]^T ---
    {
        dim3 grid(DD / 64, M / 64, 1);
        // q = scale * (x2 @ Wk^T)   (weights are swapped in the reference!)
        gemm_tn<<<grid, blk>>>(x2, DD, 0, 0, Wk, DD, 0, 0, q, DD, 0, 0,
                               DD, scale, nullptr, 1);
        // key = scale * (x1 @ Wq^T)
        gemm_tn<<<grid, blk>>>(x1, DD, 0, 0, Wq, DD, 0, 0, k, DD, 0, 0,
                               DD, scale, nullptr, 1);
        // v = x0 @ Wv^T
        gemm_tn<<<grid, blk>>>(x0, DD, 0, 0, Wv, DD, 0, 0, v, DD, 0, 0,
                               DD, 1.0f, nullptr, 1);
    }

    // --- scores[b,h,l,m] = q[b,l,h,:] . k[b,m,h,:] ---
    {
        dim3 grid(LL / 64, LL / 64, BB * HH);
        gemm_tn<<<grid, blk>>>(q, DD, (long)LL * DD, KHD,
                               k, DD, (long)LL * DD, KHD,
                               sc, LL, (long)HH * LL * LL, (long)LL * LL,
                               KHD, 1.0f, nullptr, HH);
    }

    // --- softmax over m ---
    softmax_rows<<<BB * HH * LL, 256>>>(sc);

    // --- att[b,l,h,:] = sum_m attn[b,h,l,m] * v[b,m,h,:] ---
    {
        dim3 grid(KHD / 64, LL / 64, BB * HH);
        gemm_nn<<<grid, blk>>>(sc, LL, (long)HH * LL * LL, (long)LL * LL,
                               v, DD, (long)LL * DD, KHD,
                               att, DD, (long)LL * DD, KHD,
                               LL, HH);
    }

    // --- unify: uni = att @ Wu^T + bu ---
    {
        dim3 grid(DD / 64, M / 64, 1);
        gemm_tn<<<grid, blk>>>(att, DD, 0, 0, Wu, DD, 0, 0, uni, DD, 0, 0,
                               DD, 1.0f, bu, 1);
    }

    // --- pool (mean + max over L) ---
    {
        dim3 grid(DD / 256, BB);
        pool_kernel<<<grid, 256>>>(uni, pool);
    }

    // --- logits ---
    logits_kernel<<<BB, 256>>>(pool, Wmlp, bmlp, out);
}

// round 2
// speedup vs baseline: 1.8031x; 1.8031x over previous
#include <cuda_runtime.h>
#include <math.h>
#include <stdint.h>

#define BB   16
#define LL   1024
#define DD   1024
#define HH   8
#define KHD  128
#define OUTN 64

// -------- scratch (device globals) --------
__device__ float g_q  [BB * LL * DD];
__device__ float g_k  [BB * LL * DD];
__device__ float g_v  [BB * LL * DD];
__device__ float g_sc [(long)BB * HH * LL * LL];   // 512 MB
__device__ float g_att[BB * LL * DD];
__device__ float g_uni[BB * LL * DD];
__device__ float g_pool[BB * DD];

#define BKP 20   // padded smem k-stride (conflict-free for frag loads, 16B-aligned stores)

__device__ __forceinline__ void mma_tf32(float* c,
    uint32_t a0, uint32_t a1, uint32_t a2, uint32_t a3,
    uint32_t b0, uint32_t b1)
{
    asm volatile(
        "mma.sync.aligned.m16n8k8.row.col.f32.tf32.tf32.f32 "
        "{%0,%1,%2,%3},{%4,%5,%6,%7},{%8,%9},{%0,%1,%2,%3};"
        : "+f"(c[0]), "+f"(c[1]), "+f"(c[2]), "+f"(c[3])
        : "r"(a0), "r"(a1), "r"(a2), "r"(a3), "r"(b0), "r"(b1));
}

__device__ __forceinline__ void split1(float x, float& hi, float& lo)
{
    hi = __uint_as_float(__float_as_uint(x) & 0xffffe000u);
    lo = x - hi;
}

// =================================================================
// 3xTF32 GEMM, BM=BN=128, BK=16, 256 threads (8 warps, 2x4),
// warp tile 64x32 (4x4 m16n8k8 tiles), fp32 accumulate.
// BNN=false: C[m,n] = alpha*sum_k A[m,k]*B[n,k] (+bias)   (x @ W^T / Q K^T)
// BNN=true : C[m,n] = alpha*sum_k A[m,k]*B[k,n]           (attn @ V)
// Batched via blockIdx.z with per-tensor strides.
// =================================================================
template<bool BNN>
__global__ void __launch_bounds__(256)
gemm3(const float* __restrict__ A, int lda, long sA1, long sA2,
      const float* __restrict__ B, int ldb, long sB1, long sB2,
      float* __restrict__ C, int ldc, long sC1, long sC2,
      int Kd, float alpha, const float* __restrict__ bias, int hdiv)
{
    __shared__ float As_hi[128 * BKP];
    __shared__ float As_lo[128 * BKP];
    __shared__ float Bs_hi[128 * BKP];
    __shared__ float Bs_lo[128 * BKP];

    const int z = blockIdx.z, zb = z / hdiv, zh = z % hdiv;
    A += (long)zb * sA1 + (long)zh * sA2;
    B += (long)zb * sB1 + (long)zh * sB2;
    C += (long)zb * sC1 + (long)zh * sC2;

    const int bm = blockIdx.y * 128, bn = blockIdx.x * 128;
    const int u = threadIdx.x;
    const int wid = u >> 5, lane = u & 31;
    const int wm = (wid >> 2) * 64, wn = (wid & 3) * 32;
    const int tr = lane >> 2, tc = lane & 3;

    float acc[4][4][4];
    #pragma unroll
    for (int i = 0; i < 4; ++i)
        #pragma unroll
        for (int j = 0; j < 4; ++j)
            #pragma unroll
            for (int p = 0; p < 4; ++p) acc[i][j][p] = 0.f;

    // ---- staging helpers ----
    const int ar = u >> 2, ac = (u & 3) * 4;             // A loader: 64 rows x 4 k
    const int bkk = u >> 4, bn0 = (u & 15) * 8;          // B NN loader

    auto ldgA = [&](int k0, float4& r0, float4& r1) {
        const float* p = A + (long)(bm + ar) * lda + k0 + ac;
        r0 = *(const float4*)p;
        r1 = *(const float4*)(p + (long)64 * lda);
    };
    auto ldgB = [&](int k0, float4& r0, float4& r1) {
        if (!BNN) {
            const float* p = B + (long)(bn + ar) * ldb + k0 + ac;
            r0 = *(const float4*)p;
            r1 = *(const float4*)(p + (long)64 * ldb);
        } else {
            const float* p = B + (long)(k0 + bkk) * ldb + bn + bn0;
            r0 = *(const float4*)p;
            r1 = *(const float4*)(p + 4);
        }
    };
    auto sts4 = [&](float* hiArr, float* loArr, int idx, float4 r) {
        float4 h, l;
        split1(r.x, h.x, l.x); split1(r.y, h.y, l.y);
        split1(r.z, h.z, l.z); split1(r.w, h.w, l.w);
        *(float4*)&hiArr[idx] = h;
        *(float4*)&loArr[idx] = l;
    };
    auto stsA = [&](float4 r0, float4 r1) {
        sts4(As_hi, As_lo, ar * BKP + ac, r0);
        sts4(As_hi, As_lo, (ar + 64) * BKP + ac, r1);
    };
    auto stsB = [&](float4 r0, float4 r1) {
        if (!BNN) {
            sts4(Bs_hi, Bs_lo, ar * BKP + ac, r0);
            sts4(Bs_hi, Bs_lo, (ar + 64) * BKP + ac, r1);
        } else {
            float h, l;
            const float* e0 = (const float*)&r0;
            const float* e1 = (const float*)&r1;
            #pragma unroll
            for (int j = 0; j < 4; ++j) {
                split1(e0[j], h, l);
                Bs_hi[(bn0 + j) * BKP + bkk] = h;
                Bs_lo[(bn0 + j) * BKP + bkk] = l;
            }
            #pragma unroll
            for (int j = 0; j < 4; ++j) {
                split1(e1[j], h, l);
                Bs_hi[(bn0 + 4 + j) * BKP + bkk] = h;
                Bs_lo[(bn0 + 4 + j) * BKP + bkk] = l;
            }
        }
    };

    const int nstage = Kd >> 4;
    {
        float4 a0, a1, b0, b1;
        ldgA(0, a0, a1);
        ldgB(0, b0, b1);
        stsA(a0, a1);
        stsB(b0, b1);
    }

    for (int s = 0; s < nstage; ++s) {
        __syncthreads();

        float4 na0, na1, nb0, nb1;
        if (s + 1 < nstage) {
            ldgA((s + 1) * 16, na0, na1);
            ldgB((s + 1) * 16, nb0, nb1);
        }

        #pragma unroll
        for (int kk = 0; kk < 16; kk += 8) {
            uint32_t ah[4][4], al[4][4];
            #pragma unroll
            for (int mt = 0; mt < 4; ++mt) {
                const int base = (wm + mt * 16 + tr) * BKP + kk + tc;
                ah[mt][0] = __float_as_uint(As_hi[base]);
                ah[mt][1] = __float_as_uint(As_hi[base + 8 * BKP]);
                ah[mt][2] = __float_as_uint(As_hi[base + 4]);
                ah[mt][3] = __float_as_uint(As_hi[base + 8 * BKP + 4]);
                al[mt][0] = __float_as_uint(As_lo[base]);
                al[mt][1] = __float_as_uint(As_lo[base + 8 * BKP]);
                al[mt][2] = __float_as_uint(As_lo[base + 4]);
                al[mt][3] = __float_as_uint(As_lo[base + 8 * BKP + 4]);
            }
            #pragma unroll
            for (int nt = 0; nt < 4; ++nt) {
                const int bbase = (wn + nt * 8 + tr) * BKP + kk + tc;
                const uint32_t bh0 = __float_as_uint(Bs_hi[bbase]);
                const uint32_t bh1 = __float_as_uint(Bs_hi[bbase + 4]);
                const uint32_t bl0 = __float_as_uint(Bs_lo[bbase]);
                const uint32_t bl1 = __float_as_uint(Bs_lo[bbase + 4]);
                #pragma unroll
                for (int mt = 0; mt < 4; ++mt) {
                    float* c = acc[mt][nt];
                    mma_tf32(c, ah[mt][0], ah[mt][1], ah[mt][2], ah[mt][3], bh0, bh1);
                    mma_tf32(c, ah[mt][0], ah[mt][1], ah[mt][2], ah[mt][3], bl0, bl1);
                    mma_tf32(c, al[mt][0], al[mt][1], al[mt][2], al[mt][3], bh0, bh1);
                }
            }
        }

        __syncthreads();
        if (s + 1 < nstage) {
            stsA(na0, na1);
            stsB(nb0, nb1);
        }
    }

    // ---- epilogue ----
    #pragma unroll
    for (int mt = 0; mt < 4; ++mt) {
        const int row = bm + wm + mt * 16 + tr;
        #pragma unroll
        for (int nt = 0; nt < 4; ++nt) {
            const int col = bn + wn + nt * 8 + tc * 2;
            float bx = 0.f, by = 0.f;
            if (bias) { bx = __ldg(bias + col); by = __ldg(bias + col + 1); }
            const float* c = acc[mt][nt];
            float2 v0 = make_float2(c[0] * alpha + bx, c[1] * alpha + by);
            float2 v1 = make_float2(c[2] * alpha + bx, c[3] * alpha + by);
            *(float2*)&C[(long)row * ldc + col] = v0;
            *(float2*)&C[(long)(row + 8) * ldc + col] = v1;
        }
    }
}

// =================================================================
// Row softmax over last dim (LL), one block per row.
// =================================================================
__global__ void softmax_rows(float* __restrict__ sc)
{
    float* p = sc + (long)blockIdx.x * LL;
    const int t = threadIdx.x;
    __shared__ float red[8];

    float mx = -1e30f;
    #pragma unroll
    for (int i = t; i < LL; i += 256) mx = fmaxf(mx, p[i]);
    #pragma unroll
    for (int o = 16; o; o >>= 1) mx = fmaxf(mx, __shfl_xor_sync(~0u, mx, o));
    if ((t & 31) == 0) red[t >> 5] = mx;
    __syncthreads();
    if (t < 32) {
        float v = (t < 8) ? red[t] : -1e30f;
        #pragma unroll
        for (int o = 4; o; o >>= 1) v = fmaxf(v, __shfl_xor_sync(~0u, v, o));
        if (t == 0) red[0] = v;
    }
    __syncthreads();
    mx = red[0];
    __syncthreads();

    float s = 0.f;
    #pragma unroll
    for (int i = t; i < LL; i += 256) {
        float e = __expf(p[i] - mx);
        p[i] = e;
        s += e;
    }
    #pragma unroll
    for (int o = 16; o; o >>= 1) s += __shfl_xor_sync(~0u, s, o);
    if ((t & 31) == 0) red[t >> 5] = s;
    __syncthreads();
    if (t < 32) {
        float v = (t < 8) ? red[t] : 0.f;
        #pragma unroll
        for (int o = 4; o; o >>= 1) v += __shfl_xor_sync(~0u, v, o);
        if (t == 0) red[0] = v;
    }
    __syncthreads();
    const float inv = 1.f / red[0];
    for (int i = t; i < LL; i += 256) p[i] *= inv;
}

// =================================================================
__global__ void pool_kernel(const float* __restrict__ uni, float* __restrict__ pool)
{
    const int n = blockIdx.x * 256 + threadIdx.x;
    const int b = blockIdx.y;
    const float* p = uni + (long)b * LL * DD + n;
    float s = 0.f, m = -1e30f;
    for (int l = 0; l < LL; ++l) {
        float v = p[(long)l * DD];
        s += v;
        m = fmaxf(m, v);
    }
    pool[b * DD + n] = s * (1.f / LL) + m;
}

__global__ void logits_kernel(const float* __restrict__ pool,
                              const float* __restrict__ Wm,
                              const float* __restrict__ bm,
                              float* __restrict__ out)
{
    const int b = blockIdx.x;
    __shared__ float ps[DD];
    for (int i = threadIdx.x; i < DD; i += blockDim.x) ps[i] = pool[b * DD + i];
    __syncthreads();
    const int o = threadIdx.x;
    if (o < OUTN) {
        float s = bm[o];
        const float* w = Wm + (long)o * DD;
        for (int kk = 0; kk < DD; ++kk) s += ps[kk] * w[kk];
        out[b * OUTN + o] = s;
    }
}

// =================================================================
extern "C" void kernel_launch(void* const* d_in, const int* in_sizes, int n_in,
                              void* d_out, int out_size)
{
    const float* x0   = (const float*)d_in[0];
    const float* x1   = (const float*)d_in[1];
    const float* x2   = (const float*)d_in[2];
    const float* Wk   = (const float*)d_in[5];
    const float* Wq   = (const float*)d_in[6];
    const float* Wv   = (const float*)d_in[7];
    const float* Wu   = (const float*)d_in[8];
    const float* bu   = (const float*)d_in[9];
    const float* Wmlp = (const float*)d_in[10];
    const float* bmlp = (const float*)d_in[11];
    float* out = (float*)d_out;

    float *q, *k, *v, *sc, *att, *uni, *pool;
    cudaGetSymbolAddress((void**)&q,    g_q);
    cudaGetSymbolAddress((void**)&k,    g_k);
    cudaGetSymbolAddress((void**)&v,    g_v);
    cudaGetSymbolAddress((void**)&sc,   g_sc);
    cudaGetSymbolAddress((void**)&att,  g_att);
    cudaGetSymbolAddress((void**)&uni,  g_uni);
    cudaGetSymbolAddress((void**)&pool, g_pool);

    const float scale = powf((float)KHD, -0.25f);
    const int M = BB * LL;   // 16384
    dim3 blk(256);

    // --- QKV projections ---
    {
        dim3 grid(DD / 128, M / 128, 1);
        gemm3<false><<<grid, blk>>>(x2, DD, 0, 0, Wk, DD, 0, 0, q, DD, 0, 0,
                                    DD, scale, nullptr, 1);
        gemm3<false><<<grid, blk>>>(x1, DD, 0, 0, Wq, DD, 0, 0, k, DD, 0, 0,
                                    DD, scale, nullptr, 1);
        gemm3<false><<<grid, blk>>>(x0, DD, 0, 0, Wv, DD, 0, 0, v, DD, 0, 0,
                                    DD, 1.0f, nullptr, 1);
    }

    // --- scores[b,h,l,m] = q . k ---
    {
        dim3 grid(LL / 128, LL / 128, BB * HH);
        gemm3<false><<<grid, blk>>>(q, DD, (long)LL * DD, KHD,
                                    k, DD, (long)LL * DD, KHD,
                                    sc, LL, (long)HH * LL * LL, (long)LL * LL,
                                    KHD, 1.0f, nullptr, HH);
    }

    // --- softmax ---
    softmax_rows<<<BB * HH * LL, 256>>>(sc);

    // --- att = attn @ V ---
    {
        dim3 grid(KHD / 128, LL / 128, BB * HH);
        gemm3<true><<<grid, blk>>>(sc, LL, (long)HH * LL * LL, (long)LL * LL,
                                   v, DD, (long)LL * DD, KHD,
                                   att, DD, (long)LL * DD, KHD,
                                   LL, 1.0f, nullptr, HH);
    }

    // --- unify ---
    {
        dim3 grid(DD / 128, M / 128, 1);
        gemm3<false><<<grid, blk>>>(att, DD, 0, 0, Wu, DD, 0, 0, uni, DD, 0, 0,
                                    DD, 1.0f, bu, 1);
    }

    // --- pool + logits ---
    {
        dim3 grid(DD / 256, BB);
        pool_kernel<<<grid, 256>>>(uni, pool);
    }
    logits_kernel<<<BB, 256>>>(pool, Wmlp, bmlp, out);
}

// round 4
// speedup vs baseline: 3.3897x; 1.8799x over previous
#include <cuda_runtime.h>
#include <cuda_bf16.h>
#include <math.h>
#include <stdint.h>

#define BB 16
#define LL 1024
#define DD 1024
#define HH 8
#define KHD 128
#define OUTN 64

typedef __nv_bfloat16  bf16;
typedef __nv_bfloat162 bf162;

// ---------------- scratch (device globals) ----------------
__device__ bf16 g_x0h[BB*LL*DD], g_x0l[BB*LL*DD];
__device__ bf16 g_x1h[BB*LL*DD], g_x1l[BB*LL*DD];
__device__ bf16 g_x2h[BB*LL*DD], g_x2l[BB*LL*DD];
__device__ bf16 g_wkh[DD*DD], g_wkl[DD*DD];
__device__ bf16 g_wqh[DD*DD], g_wql[DD*DD];
__device__ bf16 g_wvh[DD*DD], g_wvl[DD*DD];
__device__ bf16 g_wuh[DD*DD], g_wul[DD*DD];
__device__ bf16 g_qh[BB*LL*DD], g_ql[BB*LL*DD];
__device__ bf16 g_kh[BB*LL*DD], g_kl[BB*LL*DD];
__device__ bf16 g_vh[BB*LL*DD], g_vl[BB*LL*DD];
__device__ float g_sc[(long)BB*HH*LL*LL];                 // 512 MB
__device__ bf16 g_ph[(long)BB*HH*LL*LL], g_pl[(long)BB*HH*LL*LL];
__device__ bf16 g_ath[BB*LL*DD], g_atl[BB*LL*DD];
__device__ float g_uni[BB*LL*DD];
__device__ float g_pool[BB*DD];

// ---------------- small helpers ----------------
__device__ __forceinline__ void bsplit(float x, bf16& h, bf16& l) {
    h = __float2bfloat16_rn(x);
    l = __float2bfloat16_rn(x - __bfloat162float(h));
}

__device__ __forceinline__ void cpa16(void* s, const void* g) {
    uint32_t sa = (uint32_t)__cvta_generic_to_shared(s);
    asm volatile("cp.async.cg.shared.global [%0], [%1], 16;" :: "r"(sa), "l"(g));
}
__device__ __forceinline__ void cp_commit() {
    asm volatile("cp.async.commit_group;" ::: "memory");
}
__device__ __forceinline__ void cp_wait1() {
    asm volatile("cp.async.wait_group 1;" ::: "memory");
}

__device__ __forceinline__ void ldsm_x4(uint32_t* r, const void* p) {
    uint32_t a = (uint32_t)__cvta_generic_to_shared(p);
    asm volatile("ldmatrix.sync.aligned.m8n8.x4.shared.b16 {%0,%1,%2,%3}, [%4];"
        : "=r"(r[0]), "=r"(r[1]), "=r"(r[2]), "=r"(r[3]) : "r"(a));
}
__device__ __forceinline__ void ldsm_x2(uint32_t* r, const void* p) {
    uint32_t a = (uint32_t)__cvta_generic_to_shared(p);
    asm volatile("ldmatrix.sync.aligned.m8n8.x2.shared.b16 {%0,%1}, [%2];"
        : "=r"(r[0]), "=r"(r[1]) : "r"(a));
}
__device__ __forceinline__ void ldsm_x2t(uint32_t* r, const void* p) {
    uint32_t a = (uint32_t)__cvta_generic_to_shared(p);
    asm volatile("ldmatrix.sync.aligned.m8n8.x2.trans.shared.b16 {%0,%1}, [%2];"
        : "=r"(r[0]), "=r"(r[1]) : "r"(a));
}

__device__ __forceinline__ void mma_bf16(float* c, const uint32_t* a, const uint32_t* b) {
    asm volatile(
        "mma.sync.aligned.m16n8k16.row.col.f32.bf16.bf16.f32 "
        "{%0,%1,%2,%3},{%4,%5,%6,%7},{%8,%9},{%0,%1,%2,%3};"
        : "+f"(c[0]), "+f"(c[1]), "+f"(c[2]), "+f"(c[3])
        : "r"(a[0]), "r"(a[1]), "r"(a[2]), "r"(a[3]), "r"(b[0]), "r"(b[1]));
}

// =================================================================
// split-bf16 3-MMA GEMM. BM=BN=128, BK=32, 256 thr (8 warps, 2x4),
// warp tile 64x32, double-buffered cp.async, ldmatrix fragments.
// BNN=false: C[m,n] = alpha*sum_k A[m,k]*B[n,k] (+bias)
// BNN=true : C[m,n] = alpha*sum_k A[m,k]*B[k,n]
// A,B pre-split into bf16 hi/lo; C optionally fp32 and/or split bf16.
// =================================================================
template<bool BNN, bool WF32, bool WBF16>
__global__ void __launch_bounds__(256)
gemm_b3(const bf16* __restrict__ Ah, const bf16* __restrict__ Al,
        int lda, long sA1, long sA2,
        const bf16* __restrict__ Bh, const bf16* __restrict__ Bl,
        int ldb, long sB1, long sB2,
        float* __restrict__ Cf, bf16* __restrict__ Ch, bf16* __restrict__ Cl,
        int ldc, long sC1, long sC2,
        int Kd, float alpha, const float* __restrict__ bias, int hdiv)
{
    extern __shared__ __align__(16) char smem[];
    constexpr int SA  = 128 * 40 * 2;                 // bytes / A array / stage
    constexpr int SB  = BNN ? 32 * 136 * 2 : 128 * 40 * 2;
    constexpr int STG = 2 * SA + 2 * SB;

    const int z = blockIdx.z, zb = z / hdiv, zh = z % hdiv;
    Ah += (long)zb * sA1 + (long)zh * sA2;
    Al += (long)zb * sA1 + (long)zh * sA2;
    Bh += (long)zb * sB1 + (long)zh * sB2;
    Bl += (long)zb * sB1 + (long)zh * sB2;
    const long coff = (long)zb * sC1 + (long)zh * sC2;
    if (WF32)  Cf += coff;
    if (WBF16) { Ch += coff; Cl += coff; }

    const int bm = blockIdx.y * 128, bn = blockIdx.x * 128;
    const int u = threadIdx.x, wid = u >> 5, lane = u & 31;
    const int wm = (wid >> 2) * 64, wn = (wid & 3) * 32;

    float acc[4][4][4];
    #pragma unroll
    for (int i = 0; i < 4; ++i)
        #pragma unroll
        for (int j = 0; j < 4; ++j)
            #pragma unroll
            for (int p = 0; p < 4; ++p) acc[i][j][p] = 0.f;

    auto stage = [&](int buf, int k0) {
        bf16* sAh = (bf16*)(smem + (long)buf * STG);
        bf16* sAl = (bf16*)(smem + (long)buf * STG + SA);
        bf16* sBh = (bf16*)(smem + (long)buf * STG + 2 * SA);
        bf16* sBl = (bf16*)(smem + (long)buf * STG + 2 * SA + SB);
        #pragma unroll
        for (int c = u; c < 512; c += 256) {
            const int row = c >> 2, seg = c & 3;
            const long go = (long)(bm + row) * lda + k0 + seg * 8;
            cpa16(sAh + row * 40 + seg * 8, Ah + go);
            cpa16(sAl + row * 40 + seg * 8, Al + go);
        }
        if (!BNN) {
            #pragma unroll
            for (int c = u; c < 512; c += 256) {
                const int row = c >> 2, seg = c & 3;
                const long go = (long)(bn + row) * ldb + k0 + seg * 8;
                cpa16(sBh + row * 40 + seg * 8, Bh + go);
                cpa16(sBl + row * 40 + seg * 8, Bl + go);
            }
        } else {
            #pragma unroll
            for (int c = u; c < 512; c += 256) {
                const int row = c >> 4, seg = c & 15;
                const long go = (long)(k0 + row) * ldb + bn + seg * 8;
                cpa16(sBh + row * 136 + seg * 8, Bh + go);
                cpa16(sBl + row * 136 + seg * 8, Bl + go);
            }
        }
    };

    const int nst = Kd >> 5;
    stage(0, 0);
    cp_commit();

    for (int s = 0; s < nst; ++s) {
        if (s + 1 < nst) stage((s + 1) & 1, (s + 1) * 32);
        cp_commit();
        cp_wait1();
        __syncthreads();

        const int buf = s & 1;
        const bf16* sAh = (const bf16*)(smem + (long)buf * STG);
        const bf16* sAl = (const bf16*)(smem + (long)buf * STG + SA);
        const bf16* sBh = (const bf16*)(smem + (long)buf * STG + 2 * SA);
        const bf16* sBl = (const bf16*)(smem + (long)buf * STG + 2 * SA + SB);

        #pragma unroll
        for (int kk = 0; kk < 32; kk += 16) {
            uint32_t ah[4][4], al[4][4];
            #pragma unroll
            for (int mt = 0; mt < 4; ++mt) {
                const int off = (wm + mt * 16 + (lane & 15)) * 40 + kk + (lane >> 4) * 8;
                ldsm_x4(ah[mt], sAh + off);
                ldsm_x4(al[mt], sAl + off);
            }
            #pragma unroll
            for (int nt = 0; nt < 4; ++nt) {
                uint32_t bh[2], bl[2];
                if (!BNN) {
                    const int l = lane & 15;
                    const int off = (wn + nt * 8 + (l & 7)) * 40 + kk + (l >> 3) * 8;
                    ldsm_x2(bh, sBh + off);
                    ldsm_x2(bl, sBl + off);
                } else {
                    const int off = (kk + (lane & 15)) * 136 + wn + nt * 8;
                    ldsm_x2t(bh, sBh + off);
                    ldsm_x2t(bl, sBl + off);
                }
                #pragma unroll
                for (int mt = 0; mt < 4; ++mt) {
                    mma_bf16(acc[mt][nt], ah[mt], bh);
                    mma_bf16(acc[mt][nt], ah[mt], bl);
                    mma_bf16(acc[mt][nt], al[mt], bh);
                }
            }
        }
        __syncthreads();
    }

    // ---- epilogue ----
    const int tr = lane >> 2, tc = lane & 3;
    #pragma unroll
    for (int mt = 0; mt < 4; ++mt) {
        const int row = bm + wm + mt * 16 + tr;
        #pragma unroll
        for (int nt = 0; nt < 4; ++nt) {
            const int col = bn + wn + nt * 8 + tc * 2;
            float b0 = 0.f, b1 = 0.f;
            if (bias) { b0 = __ldg(bias + col); b1 = __ldg(bias + col + 1); }
            const float* c = acc[mt][nt];
            const float v0 = c[0] * alpha + b0, v1 = c[1] * alpha + b1;
            const float v2 = c[2] * alpha + b0, v3 = c[3] * alpha + b1;
            if (WF32) {
                *(float2*)&Cf[(long)row * ldc + col]       = make_float2(v0, v1);
                *(float2*)&Cf[(long)(row + 8) * ldc + col] = make_float2(v2, v3);
            }
            if (WBF16) {
                bf16 h0, l0, h1, l1;
                bsplit(v0, h0, l0); bsplit(v1, h1, l1);
                bf162 hh; hh.x = h0; hh.y = h1;
                bf162 ll; ll.x = l0; ll.y = l1;
                *(bf162*)&Ch[(long)row * ldc + col] = hh;
                *(bf162*)&Cl[(long)row * ldc + col] = ll;
                bsplit(v2, h0, l0); bsplit(v3, h1, l1);
                hh.x = h0; hh.y = h1; ll.x = l0; ll.y = l1;
                *(bf162*)&Ch[(long)(row + 8) * ldc + col] = hh;
                *(bf162*)&Cl[(long)(row + 8) * ldc + col] = ll;
            }
        }
    }
}

// ---------------- fp32 -> split bf16 convert ----------------
__global__ void split_k(const float* __restrict__ in, bf16* __restrict__ hi,
                        bf16* __restrict__ lo, int n4)
{
    const int i = blockIdx.x * 256 + threadIdx.x;
    if (i >= n4) return;
    const float4 v = ((const float4*)in)[i];
    bf16 h0, l0, h1, l1, h2, l2, h3, l3;
    bsplit(v.x, h0, l0); bsplit(v.y, h1, l1);
    bsplit(v.z, h2, l2); bsplit(v.w, h3, l3);
    bf162 a, b;
    a.x = h0; a.y = h1; b.x = h2; b.y = h3;
    ((bf162*)hi)[i * 2] = a; ((bf162*)hi)[i * 2 + 1] = b;
    a.x = l0; a.y = l1; b.x = l2; b.y = l3;
    ((bf162*)lo)[i * 2] = a; ((bf162*)lo)[i * 2 + 1] = b;
}

// ---------------- softmax: fp32 scores -> split-bf16 probs ----------------
__global__ void softmax_k(const float* __restrict__ sc,
                          bf16* __restrict__ ph, bf16* __restrict__ pl)
{
    const long base = (long)blockIdx.x * LL;
    const int t = threadIdx.x;
    __shared__ float red[8];

    const float4 v = ((const float4*)(sc + base))[t];
    float mx = fmaxf(fmaxf(v.x, v.y), fmaxf(v.z, v.w));
    #pragma unroll
    for (int o = 16; o; o >>= 1) mx = fmaxf(mx, __shfl_xor_sync(~0u, mx, o));
    if ((t & 31) == 0) red[t >> 5] = mx;
    __syncthreads();
    if (t < 32) {
        float r = (t < 8) ? red[t] : -1e30f;
        #pragma unroll
        for (int o = 4; o; o >>= 1) r = fmaxf(r, __shfl_xor_sync(~0u, r, o));
        if (t == 0) red[0] = r;
    }
    __syncthreads();
    mx = red[0];
    __syncthreads();

    float e0 = __expf(v.x - mx), e1 = __expf(v.y - mx);
    float e2 = __expf(v.z - mx), e3 = __expf(v.w - mx);
    float s = e0 + e1 + e2 + e3;
    #pragma unroll
    for (int o = 16; o; o >>= 1) s += __shfl_xor_sync(~0u, s, o);
    if ((t & 31) == 0) red[t >> 5] = s;
    __syncthreads();
    if (t < 32) {
        float r = (t < 8) ? red[t] : 0.f;
        #pragma unroll
        for (int o = 4; o; o >>= 1) r += __shfl_xor_sync(~0u, r, o);
        if (t == 0) red[0] = r;
    }
    __syncthreads();
    const float inv = 1.f / red[0];

    bf16 h0, l0, h1, l1;
    bf162 hh, ll;
    bsplit(e0 * inv, h0, l0); bsplit(e1 * inv, h1, l1);
    hh.x = h0; hh.y = h1; ll.x = l0; ll.y = l1;
    ((bf162*)(ph + base))[t * 2] = hh;
    ((bf162*)(pl + base))[t * 2] = ll;
    bsplit(e2 * inv, h0, l0); bsplit(e3 * inv, h1, l1);
    hh.x = h0; hh.y = h1; ll.x = l0; ll.y = l1;
    ((bf162*)(ph + base))[t * 2 + 1] = hh;
    ((bf162*)(pl + base))[t * 2 + 1] = ll;
}

// ---------------- pool + logits ----------------
__global__ void pool_kernel(const float* __restrict__ uni, float* __restrict__ pool)
{
    const int n = blockIdx.x * 256 + threadIdx.x;
    const int b = blockIdx.y;
    const float* p = uni + (long)b * LL * DD + n;
    float s = 0.f, m = -1e30f;
    for (int l = 0; l < LL; ++l) {
        float v = p[(long)l * DD];
        s += v;
        m = fmaxf(m, v);
    }
    pool[b * DD + n] = s * (1.f / LL) + m;
}

__global__ void logits_kernel(const float* __restrict__ pool,
                              const float* __restrict__ Wm,
                              const float* __restrict__ bm,
                              float* __restrict__ out)
{
    const int b = blockIdx.x;
    __shared__ float ps[DD];
    for (int i = threadIdx.x; i < DD; i += blockDim.x) ps[i] = pool[b * DD + i];
    __syncthreads();
    const int o = threadIdx.x;
    if (o < OUTN) {
        float s = bm[o];
        const float* w = Wm + (long)o * DD;
        for (int kk = 0; kk < DD; ++kk) s += ps[kk] * w[kk];
        out[b * OUTN + o] = s;
    }
}

// =================================================================
extern "C" void kernel_launch(void* const* d_in, const int* in_sizes, int n_in,
                              void* d_out, int out_size)
{
    const float* x0   = (const float*)d_in[0];
    const float* x1   = (const float*)d_in[1];
    const float* x2   = (const float*)d_in[2];
    const float* Wk   = (const float*)d_in[5];
    const float* Wq   = (const float*)d_in[6];
    const float* Wv   = (const float*)d_in[7];
    const float* Wu   = (const float*)d_in[8];
    const float* bu   = (const float*)d_in[9];
    const float* Wmlp = (const float*)d_in[10];
    const float* bmlp = (const float*)d_in[11];
    float* out = (float*)d_out;

    bf16 *x0h,*x0l,*x1h,*x1l,*x2h,*x2l;
    bf16 *wkh,*wkl,*wqh,*wql,*wvh,*wvl,*wuh,*wul;
    bf16 *qh,*ql,*kh,*kl,*vh,*vl,*ph,*pl,*ath,*atl;
    float *sc,*uni,*pool;
    cudaGetSymbolAddress((void**)&x0h, g_x0h); cudaGetSymbolAddress((void**)&x0l, g_x0l);
    cudaGetSymbolAddress((void**)&x1h, g_x1h); cudaGetSymbolAddress((void**)&x1l, g_x1l);
    cudaGetSymbolAddress((void**)&x2h, g_x2h); cudaGetSymbolAddress((void**)&x2l, g_x2l);
    cudaGetSymbolAddress((void**)&wkh, g_wkh); cudaGetSymbolAddress((void**)&wkl, g_wkl);
    cudaGetSymbolAddress((void**)&wqh, g_wqh); cudaGetSymbolAddress((void**)&wql, g_wql);
    cudaGetSymbolAddress((void**)&wvh, g_wvh); cudaGetSymbolAddress((void**)&wvl, g_wvl);
    cudaGetSymbolAddress((void**)&wuh, g_wuh); cudaGetSymbolAddress((void**)&wul, g_wul);
    cudaGetSymbolAddress((void**)&qh,  g_qh);  cudaGetSymbolAddress((void**)&ql,  g_ql);
    cudaGetSymbolAddress((void**)&kh,  g_kh);  cudaGetSymbolAddress((void**)&kl,  g_kl);
    cudaGetSymbolAddress((void**)&vh,  g_vh);  cudaGetSymbolAddress((void**)&vl,  g_vl);
    cudaGetSymbolAddress((void**)&ph,  g_ph);  cudaGetSymbolAddress((void**)&pl,  g_pl);
    cudaGetSymbolAddress((void**)&ath, g_ath); cudaGetSymbolAddress((void**)&atl, g_atl);
    cudaGetSymbolAddress((void**)&sc,  g_sc);
    cudaGetSymbolAddress((void**)&uni, g_uni);
    cudaGetSymbolAddress((void**)&pool, g_pool);

    const float scale = powf((float)KHD, -0.25f);
    const int M = BB * LL;

    auto* kProj = gemm_b3<false, false, true>;   // split-bf16 out
    auto* kF32  = gemm_b3<false, true,  false>;  // fp32 out (+bias)
    auto* kAV   = gemm_b3<true,  false, true>;   // NN, split-bf16 out
    constexpr int SM_TN = 2 * (4 * 128 * 40 * 2);                    // 81920
    constexpr int SM_NN = 2 * (2 * 128 * 40 * 2 + 2 * 32 * 136 * 2); // 75776
    cudaFuncSetAttribute(kProj, cudaFuncAttributeMaxDynamicSharedMemorySize, SM_TN);
    cudaFuncSetAttribute(kF32,  cudaFuncAttributeMaxDynamicSharedMemorySize, SM_TN);
    cudaFuncSetAttribute(kAV,   cudaFuncAttributeMaxDynamicSharedMemorySize, SM_NN);

    // --- convert inputs to split-bf16 ---
    {
        const int nx4 = BB * LL * DD / 4, nw4 = DD * DD / 4;
        split_k<<<(nx4 + 255) / 256, 256>>>(x0, x0h, x0l, nx4);
        split_k<<<(nx4 + 255) / 256, 256>>>(x1, x1h, x1l, nx4);
        split_k<<<(nx4 + 255) / 256, 256>>>(x2, x2h, x2l, nx4);
        split_k<<<(nw4 + 255) / 256, 256>>>(Wk, wkh, wkl, nw4);
        split_k<<<(nw4 + 255) / 256, 256>>>(Wq, wqh, wql, nw4);
        split_k<<<(nw4 + 255) / 256, 256>>>(Wv, wvh, wvl, nw4);
        split_k<<<(nw4 + 255) / 256, 256>>>(Wu, wuh, wul, nw4);
    }

    dim3 blk(256);

    // --- QKV projections (write split-bf16) ---
    {
        dim3 grid(DD / 128, M / 128, 1);
        kProj<<<grid, blk, SM_TN>>>(x2h, x2l, DD, 0, 0, wkh, wkl, DD, 0, 0,
                                    nullptr, qh, ql, DD, 0, 0, DD, scale, nullptr, 1);
        kProj<<<grid, blk, SM_TN>>>(x1h, x1l, DD, 0, 0, wqh, wql, DD, 0, 0,
                                    nullptr, kh, kl, DD, 0, 0, DD, scale, nullptr, 1);
        kProj<<<grid, blk, SM_TN>>>(x0h, x0l, DD, 0, 0, wvh, wvl, DD, 0, 0,
                                    nullptr, vh, vl, DD, 0, 0, DD, 1.0f, nullptr, 1);
    }

    // --- scores (fp32 out) ---
    {
        dim3 grid(LL / 128, LL / 128, BB * HH);
        kF32<<<grid, blk, SM_TN>>>(qh, ql, DD, (long)LL * DD, KHD,
                                   kh, kl, DD, (long)LL * DD, KHD,
                                   sc, nullptr, nullptr, LL,
                                   (long)HH * LL * LL, (long)LL * LL,
                                   KHD, 1.0f, nullptr, HH);
    }

    // --- softmax -> split-bf16 probs ---
    softmax_k<<<BB * HH * LL, 256>>>(sc, ph, pl);

    // --- att = probs @ V (split-bf16 out) ---
    {
        dim3 grid(KHD / 128, LL / 128, BB * HH);
        kAV<<<grid, blk, SM_NN>>>(ph, pl, LL, (long)HH * LL * LL, (long)LL * LL,
                                  vh, vl, DD, (long)LL * DD, KHD,
                                  nullptr, ath, atl, DD, (long)LL * DD, KHD,
                                  LL, 1.0f, nullptr, HH);
    }

    // --- unify (fp32 out + bias) ---
    {
        dim3 grid(DD / 128, M / 128, 1);
        kF32<<<grid, blk, SM_TN>>>(ath, atl, DD, 0, 0, wuh, wul, DD, 0, 0,
                                   uni, nullptr, nullptr, DD, 0, 0,
                                   DD, 1.0f, bu, 1);
    }

    // --- pool + logits ---
    {
        dim3 grid(DD / 256, BB);
        pool_kernel<<<grid, 256>>>(uni, pool);
    }
    logits_kernel<<<BB, 256>>>(pool, Wmlp, bmlp, out);
}

// round 5
// speedup vs baseline: 3.9888x; 1.1768x over previous
#include <cuda_runtime.h>
#include <cuda_bf16.h>
#include <math.h>
#include <stdint.h>

#define BB 16
#define LL 1024
#define DD 1024
#define HH 8
#define KHD 128
#define OUTN 64

typedef __nv_bfloat16  bf16;
typedef __nv_bfloat162 bf162;

// ---------------- scratch (device globals) ----------------
__device__ bf16 g_x0h[BB*LL*DD], g_x0l[BB*LL*DD];
__device__ bf16 g_x1h[BB*LL*DD], g_x1l[BB*LL*DD];
__device__ bf16 g_x2h[BB*LL*DD], g_x2l[BB*LL*DD];
__device__ bf16 g_wkh[DD*DD], g_wkl[DD*DD];
__device__ bf16 g_wqh[DD*DD], g_wql[DD*DD];
__device__ bf16 g_wvh[DD*DD], g_wvl[DD*DD];
__device__ bf16 g_wuh[DD*DD], g_wul[DD*DD];
__device__ bf16 g_qh[BB*LL*DD], g_ql[BB*LL*DD];
__device__ bf16 g_kh[BB*LL*DD], g_kl[BB*LL*DD];
__device__ bf16 g_vh[BB*LL*DD], g_vl[BB*LL*DD];
__device__ bf16 g_ath[BB*LL*DD], g_atl[BB*LL*DD];
__device__ float g_uni[BB*LL*DD];
__device__ float g_pool[BB*DD];

// ---------------- helpers ----------------
__device__ __forceinline__ void bsplit(float x, bf16& h, bf16& l) {
    h = __float2bfloat16_rn(x);
    l = __float2bfloat16_rn(x - __bfloat162float(h));
}
__device__ __forceinline__ uint32_t pk(bf16 x, bf16 y) {
    bf162 t; t.x = x; t.y = y; return *(uint32_t*)&t;
}
__device__ __forceinline__ void cpa16(void* s, const void* g) {
    uint32_t sa = (uint32_t)__cvta_generic_to_shared(s);
    asm volatile("cp.async.cg.shared.global [%0], [%1], 16;" :: "r"(sa), "l"(g));
}
__device__ __forceinline__ void cp_commit() {
    asm volatile("cp.async.commit_group;" ::: "memory");
}
__device__ __forceinline__ void cp_wait1() {
    asm volatile("cp.async.wait_group 1;" ::: "memory");
}
__device__ __forceinline__ void ldsm_x4(uint32_t* r, const void* p) {
    uint32_t a = (uint32_t)__cvta_generic_to_shared(p);
    asm volatile("ldmatrix.sync.aligned.m8n8.x4.shared.b16 {%0,%1,%2,%3}, [%4];"
        : "=r"(r[0]), "=r"(r[1]), "=r"(r[2]), "=r"(r[3]) : "r"(a));
}
__device__ __forceinline__ void ldsm_x2(uint32_t* r, const void* p) {
    uint32_t a = (uint32_t)__cvta_generic_to_shared(p);
    asm volatile("ldmatrix.sync.aligned.m8n8.x2.shared.b16 {%0,%1}, [%2];"
        : "=r"(r[0]), "=r"(r[1]) : "r"(a));
}
__device__ __forceinline__ void ldsm_x2t(uint32_t* r, const void* p) {
    uint32_t a = (uint32_t)__cvta_generic_to_shared(p);
    asm volatile("ldmatrix.sync.aligned.m8n8.x2.trans.shared.b16 {%0,%1}, [%2];"
        : "=r"(r[0]), "=r"(r[1]) : "r"(a));
}
__device__ __forceinline__ void mma_bf16(float* c, const uint32_t* a, const uint32_t* b) {
    asm volatile(
        "mma.sync.aligned.m16n8k16.row.col.f32.bf16.bf16.f32 "
        "{%0,%1,%2,%3},{%4,%5,%6,%7},{%8,%9},{%0,%1,%2,%3};"
        : "+f"(c[0]), "+f"(c[1]), "+f"(c[2]), "+f"(c[3])
        : "r"(a[0]), "r"(a[1]), "r"(a[2]), "r"(a[3]), "r"(b[0]), "r"(b[1]));
}

// =================================================================
// split-bf16 3-MMA TN GEMM (unchanged from R4). BM=BN=128, BK=32.
// =================================================================
template<bool WF32, bool WBF16>
__global__ void __launch_bounds__(256)
gemm_b3(const bf16* __restrict__ Ah, const bf16* __restrict__ Al, int lda,
        const bf16* __restrict__ Bh, const bf16* __restrict__ Bl, int ldb,
        float* __restrict__ Cf, bf16* __restrict__ Ch, bf16* __restrict__ Cl,
        int ldc, int Kd, float alpha, const float* __restrict__ bias)
{
    extern __shared__ __align__(16) char smem[];
    constexpr int SA  = 128 * 40 * 2;
    constexpr int STG = 4 * SA;

    const int bm = blockIdx.y * 128, bn = blockIdx.x * 128;
    const int u = threadIdx.x, wid = u >> 5, lane = u & 31;
    const int wm = (wid >> 2) * 64, wn = (wid & 3) * 32;

    float acc[4][4][4];
    #pragma unroll
    for (int i = 0; i < 4; ++i)
        #pragma unroll
        for (int j = 0; j < 4; ++j)
            #pragma unroll
            for (int p = 0; p < 4; ++p) acc[i][j][p] = 0.f;

    auto stage = [&](int buf, int k0) {
        bf16* sAh = (bf16*)(smem + (long)buf * STG);
        bf16* sAl = (bf16*)(smem + (long)buf * STG + SA);
        bf16* sBh = (bf16*)(smem + (long)buf * STG + 2 * SA);
        bf16* sBl = (bf16*)(smem + (long)buf * STG + 3 * SA);
        #pragma unroll
        for (int c = u; c < 512; c += 256) {
            const int row = c >> 2, seg = c & 3;
            const long ga = (long)(bm + row) * lda + k0 + seg * 8;
            const long gb = (long)(bn + row) * ldb + k0 + seg * 8;
            cpa16(sAh + row * 40 + seg * 8, Ah + ga);
            cpa16(sAl + row * 40 + seg * 8, Al + ga);
            cpa16(sBh + row * 40 + seg * 8, Bh + gb);
            cpa16(sBl + row * 40 + seg * 8, Bl + gb);
        }
    };

    const int nst = Kd >> 5;
    stage(0, 0);
    cp_commit();

    for (int s = 0; s < nst; ++s) {
        if (s + 1 < nst) stage((s + 1) & 1, (s + 1) * 32);
        cp_commit();
        cp_wait1();
        __syncthreads();

        const int buf = s & 1;
        const bf16* sAh = (const bf16*)(smem + (long)buf * STG);
        const bf16* sAl = (const bf16*)(smem + (long)buf * STG + SA);
        const bf16* sBh = (const bf16*)(smem + (long)buf * STG + 2 * SA);
        const bf16* sBl = (const bf16*)(smem + (long)buf * STG + 3 * SA);

        #pragma unroll
        for (int kk = 0; kk < 32; kk += 16) {
            uint32_t ah[4][4], al[4][4];
            #pragma unroll
            for (int mt = 0; mt < 4; ++mt) {
                const int off = (wm + mt * 16 + (lane & 15)) * 40 + kk + (lane >> 4) * 8;
                ldsm_x4(ah[mt], sAh + off);
                ldsm_x4(al[mt], sAl + off);
            }
            #pragma unroll
            for (int nt = 0; nt < 4; ++nt) {
                uint32_t bh[2], bl[2];
                const int l = lane & 15;
                const int off = (wn + nt * 8 + (l & 7)) * 40 + kk + (l >> 3) * 8;
                ldsm_x2(bh, sBh + off);
                ldsm_x2(bl, sBl + off);
                #pragma unroll
                for (int mt = 0; mt < 4; ++mt) {
                    mma_bf16(acc[mt][nt], ah[mt], bh);
                    mma_bf16(acc[mt][nt], ah[mt], bl);
                    mma_bf16(acc[mt][nt], al[mt], bh);
                }
            }
        }
        __syncthreads();
    }

    const int tr = lane >> 2, tc = lane & 3;
    #pragma unroll
    for (int mt = 0; mt < 4; ++mt) {
        const int row = bm + wm + mt * 16 + tr;
        #pragma unroll
        for (int nt = 0; nt < 4; ++nt) {
            const int col = bn + wn + nt * 8 + tc * 2;
            float b0 = 0.f, b1 = 0.f;
            if (bias) { b0 = __ldg(bias + col); b1 = __ldg(bias + col + 1); }
            const float* c = acc[mt][nt];
            const float v0 = c[0] * alpha + b0, v1 = c[1] * alpha + b1;
            const float v2 = c[2] * alpha + b0, v3 = c[3] * alpha + b1;
            if (WF32) {
                *(float2*)&Cf[(long)row * ldc + col]       = make_float2(v0, v1);
                *(float2*)&Cf[(long)(row + 8) * ldc + col] = make_float2(v2, v3);
            }
            if (WBF16) {
                bf16 h0, l0, h1, l1;
                bsplit(v0, h0, l0); bsplit(v1, h1, l1);
                *(uint32_t*)&Ch[(long)row * ldc + col] = pk(h0, h1);
                *(uint32_t*)&Cl[(long)row * ldc + col] = pk(l0, l1);
                bsplit(v2, h0, l0); bsplit(v3, h1, l1);
                *(uint32_t*)&Ch[(long)(row + 8) * ldc + col] = pk(h0, h1);
                *(uint32_t*)&Cl[(long)(row + 8) * ldc + col] = pk(l0, l1);
            }
        }
    }
}

// =================================================================
// Fused flash attention: per CTA = (b,h,q-tile of 128 rows).
// Q resident in smem; 16 KV tiles of 64 streamed (double-buffered).
// S fp32, online softmax, P split-bf16 in regs, 3-MMA both GEMMs.
// 8 warps; warp w owns q rows [16w,16w+16), full kv/d extent.
// =================================================================
__global__ void __launch_bounds__(256)
flash_k(const bf16* __restrict__ Qh, const bf16* __restrict__ Ql,
        const bf16* __restrict__ Kh, const bf16* __restrict__ Kl,
        const bf16* __restrict__ Vh, const bf16* __restrict__ Vl,
        bf16* __restrict__ Oh, bf16* __restrict__ Ol)
{
    extern __shared__ __align__(16) char sm[];
    constexpr int QS = 128 * 136;   // elems per Q array
    constexpr int TS = 64 * 136;    // elems per KV array per stage
    bf16* sQh = (bf16*)sm;
    bf16* sQl = sQh + QS;
    bf16* sT  = sQl + QS;           // [2 stages][Kh,Kl,Vh,Vl][TS]

    const int bh = blockIdx.y, b = bh >> 3, h = bh & 7;
    const int q0 = blockIdx.x * 128;
    const int u = threadIdx.x, wid = u >> 5, lane = u & 31;
    const int tr = lane >> 2, tc = lane & 3;

    const long qg = ((long)b * LL + q0) * DD + h * KHD;
    const long kg = (long)b * LL * DD + h * KHD;

    // Q tile load (once)
    for (int c = u; c < 2048; c += 256) {
        const int r = c >> 4, s = (c & 15) * 8;
        cpa16(sQh + r * 136 + s, Qh + qg + (long)r * DD + s);
        cpa16(sQl + r * 136 + s, Ql + qg + (long)r * DD + s);
    }
    auto stage = [&](int buf, int kv0) {
        bf16* p = sT + buf * 4 * TS;
        for (int c = u; c < 1024; c += 256) {
            const int r = c >> 4, s = (c & 15) * 8;
            const long g = kg + (long)(kv0 + r) * DD + s;
            cpa16(p          + r * 136 + s, Kh + g);
            cpa16(p + TS     + r * 136 + s, Kl + g);
            cpa16(p + 2 * TS + r * 136 + s, Vh + g);
            cpa16(p + 3 * TS + r * 136 + s, Vl + g);
        }
    };
    stage(0, 0);
    cp_commit();

    float O[16][4];
    #pragma unroll
    for (int i = 0; i < 16; ++i)
        #pragma unroll
        for (int j = 0; j < 4; ++j) O[i][j] = 0.f;
    float m0 = -1e30f, m1 = -1e30f, l0 = 0.f, l1 = 0.f;

    for (int t = 0; t < 16; ++t) {
        if (t + 1 < 16) stage((t + 1) & 1, (t + 1) * 64);
        cp_commit();
        cp_wait1();
        __syncthreads();

        const bf16* cKh = sT + (t & 1) * 4 * TS;
        const bf16* cKl = cKh + TS;
        const bf16* cVh = cKh + 2 * TS;
        const bf16* cVl = cKh + 3 * TS;

        // ---- S = Q K^T (fp32, 3-MMA) ----
        float S[8][4];
        #pragma unroll
        for (int i = 0; i < 8; ++i)
            #pragma unroll
            for (int j = 0; j < 4; ++j) S[i][j] = 0.f;

        #pragma unroll
        for (int kk = 0; kk < 128; kk += 16) {
            uint32_t ah[4], al[4];
            const int aoff = (wid * 16 + (lane & 15)) * 136 + kk + (lane >> 4) * 8;
            ldsm_x4(ah, sQh + aoff);
            ldsm_x4(al, sQl + aoff);
            #pragma unroll
            for (int nt = 0; nt < 8; ++nt) {
                uint32_t bh2[2], bl2[2];
                const int l = lane & 15;
                const int boff = (nt * 8 + (l & 7)) * 136 + kk + (l >> 3) * 8;
                ldsm_x2(bh2, cKh + boff);
                ldsm_x2(bl2, cKl + boff);
                mma_bf16(S[nt], ah, bh2);
                mma_bf16(S[nt], ah, bl2);
                mma_bf16(S[nt], al, bh2);
            }
        }

        // ---- online softmax ----
        float rm0 = -1e30f, rm1 = -1e30f;
        #pragma unroll
        for (int nt = 0; nt < 8; ++nt) {
            rm0 = fmaxf(rm0, fmaxf(S[nt][0], S[nt][1]));
            rm1 = fmaxf(rm1, fmaxf(S[nt][2], S[nt][3]));
        }
        rm0 = fmaxf(rm0, __shfl_xor_sync(~0u, rm0, 1));
        rm0 = fmaxf(rm0, __shfl_xor_sync(~0u, rm0, 2));
        rm1 = fmaxf(rm1, __shfl_xor_sync(~0u, rm1, 1));
        rm1 = fmaxf(rm1, __shfl_xor_sync(~0u, rm1, 2));
        const float M0 = fmaxf(m0, rm0), M1 = fmaxf(m1, rm1);
        const float f0 = __expf(m0 - M0), f1 = __expf(m1 - M1);
        m0 = M0; m1 = M1;
        l0 *= f0; l1 *= f1;
        #pragma unroll
        for (int dt = 0; dt < 16; ++dt) {
            O[dt][0] *= f0; O[dt][1] *= f0;
            O[dt][2] *= f1; O[dt][3] *= f1;
        }

        // ---- P = exp(S-M); P·V (3-MMA), per 16-wide kv chunk ----
        #pragma unroll
        for (int kc = 0; kc < 4; ++kc) {
            uint32_t pah[4], pal[4];
            #pragma unroll
            for (int half = 0; half < 2; ++half) {
                const int nt = kc * 2 + half;
                const float p0 = __expf(S[nt][0] - M0);
                const float p1 = __expf(S[nt][1] - M0);
                const float p2 = __expf(S[nt][2] - M1);
                const float p3 = __expf(S[nt][3] - M1);
                l0 += p0 + p1; l1 += p2 + p3;
                bf16 h0, q0_, h1, q1_, h2, q2_, h3, q3_;
                bsplit(p0, h0, q0_); bsplit(p1, h1, q1_);
                bsplit(p2, h2, q2_); bsplit(p3, h3, q3_);
                pah[half ? 2 : 0] = pk(h0, h1);
                pah[half ? 3 : 1] = pk(h2, h3);
                pal[half ? 2 : 0] = pk(q0_, q1_);
                pal[half ? 3 : 1] = pk(q2_, q3_);
            }
            #pragma unroll
            for (int dt = 0; dt < 16; ++dt) {
                uint32_t bvh[2], bvl[2];
                const int voff = (kc * 16 + (lane & 15)) * 136 + dt * 8;
                ldsm_x2t(bvh, cVh + voff);
                ldsm_x2t(bvl, cVl + voff);
                mma_bf16(O[dt], pah, bvh);
                mma_bf16(O[dt], pah, bvl);
                mma_bf16(O[dt], pal, bvh);
            }
        }
        __syncthreads();
    }

    // ---- epilogue: normalize + write split-bf16 att ----
    l0 += __shfl_xor_sync(~0u, l0, 1); l0 += __shfl_xor_sync(~0u, l0, 2);
    l1 += __shfl_xor_sync(~0u, l1, 1); l1 += __shfl_xor_sync(~0u, l1, 2);
    const float i0 = 1.f / l0, i1 = 1.f / l1;
    const long og = ((long)b * LL + q0 + wid * 16) * DD + h * KHD;
    #pragma unroll
    for (int dt = 0; dt < 16; ++dt) {
        const int col = dt * 8 + tc * 2;
        bf16 h0, lo0, h1, lo1;
        bsplit(O[dt][0] * i0, h0, lo0); bsplit(O[dt][1] * i0, h1, lo1);
        *(uint32_t*)&Oh[og + (long)tr * DD + col] = pk(h0, h1);
        *(uint32_t*)&Ol[og + (long)tr * DD + col] = pk(lo0, lo1);
        bsplit(O[dt][2] * i1, h0, lo0); bsplit(O[dt][3] * i1, h1, lo1);
        *(uint32_t*)&Oh[og + (long)(tr + 8) * DD + col] = pk(h0, h1);
        *(uint32_t*)&Ol[og + (long)(tr + 8) * DD + col] = pk(lo0, lo1);
    }
}

// ---------------- fp32 -> split bf16 convert ----------------
__global__ void split_k(const float* __restrict__ in, bf16* __restrict__ hi,
                        bf16* __restrict__ lo, int n4)
{
    const int i = blockIdx.x * 256 + threadIdx.x;
    if (i >= n4) return;
    const float4 v = ((const float4*)in)[i];
    bf16 h0, l0, h1, l1, h2, l2, h3, l3;
    bsplit(v.x, h0, l0); bsplit(v.y, h1, l1);
    bsplit(v.z, h2, l2); bsplit(v.w, h3, l3);
    ((uint32_t*)hi)[i * 2]     = pk(h0, h1);
    ((uint32_t*)hi)[i * 2 + 1] = pk(h2, h3);
    ((uint32_t*)lo)[i * 2]     = pk(l0, l1);
    ((uint32_t*)lo)[i * 2 + 1] = pk(l2, l3);
}

// ---------------- pool + logits ----------------
__global__ void pool_kernel(const float* __restrict__ uni, float* __restrict__ pool)
{
    const int n = blockIdx.x * 256 + threadIdx.x;
    const int b = blockIdx.y;
    const float* p = uni + (long)b * LL * DD + n;
    float s = 0.f, m = -1e30f;
    for (int l = 0; l < LL; ++l) {
        float v = p[(long)l * DD];
        s += v;
        m = fmaxf(m, v);
    }
    pool[b * DD + n] = s * (1.f / LL) + m;
}

__global__ void logits_kernel(const float* __restrict__ pool,
                              const float* __restrict__ Wm,
                              const float* __restrict__ bm,
                              float* __restrict__ out)
{
    const int b = blockIdx.x;
    __shared__ float ps[DD];
    for (int i = threadIdx.x; i < DD; i += blockDim.x) ps[i] = pool[b * DD + i];
    __syncthreads();
    const int o = threadIdx.x;
    if (o < OUTN) {
        float s = bm[o];
        const float* w = Wm + (long)o * DD;
        for (int kk = 0; kk < DD; ++kk) s += ps[kk] * w[kk];
        out[b * OUTN + o] = s;
    }
}

// =================================================================
extern "C" void kernel_launch(void* const* d_in, const int* in_sizes, int n_in,
                              void* d_out, int out_size)
{
    const float* x0   = (const float*)d_in[0];
    const float* x1   = (const float*)d_in[1];
    const float* x2   = (const float*)d_in[2];
    const float* Wk   = (const float*)d_in[5];
    const float* Wq   = (const float*)d_in[6];
    const float* Wv   = (const float*)d_in[7];
    const float* Wu   = (const float*)d_in[8];
    const float* bu   = (const float*)d_in[9];
    const float* Wmlp = (const float*)d_in[10];
    const float* bmlp = (const float*)d_in[11];
    float* out = (float*)d_out;

    bf16 *x0h,*x0l,*x1h,*x1l,*x2h,*x2l;
    bf16 *wkh,*wkl,*wqh,*wql,*wvh,*wvl,*wuh,*wul;
    bf16 *qh,*ql,*kh,*kl,*vh,*vl,*ath,*atl;
    float *uni,*pool;
    cudaGetSymbolAddress((void**)&x0h, g_x0h); cudaGetSymbolAddress((void**)&x0l, g_x0l);
    cudaGetSymbolAddress((void**)&x1h, g_x1h); cudaGetSymbolAddress((void**)&x1l, g_x1l);
    cudaGetSymbolAddress((void**)&x2h, g_x2h); cudaGetSymbolAddress((void**)&x2l, g_x2l);
    cudaGetSymbolAddress((void**)&wkh, g_wkh); cudaGetSymbolAddress((void**)&wkl, g_wkl);
    cudaGetSymbolAddress((void**)&wqh, g_wqh); cudaGetSymbolAddress((void**)&wql, g_wql);
    cudaGetSymbolAddress((void**)&wvh, g_wvh); cudaGetSymbolAddress((void**)&wvl, g_wvl);
    cudaGetSymbolAddress((void**)&wuh, g_wuh); cudaGetSymbolAddress((void**)&wul, g_wul);
    cudaGetSymbolAddress((void**)&qh,  g_qh);  cudaGetSymbolAddress((void**)&ql,  g_ql);
    cudaGetSymbolAddress((void**)&kh,  g_kh);  cudaGetSymbolAddress((void**)&kl,  g_kl);
    cudaGetSymbolAddress((void**)&vh,  g_vh);  cudaGetSymbolAddress((void**)&vl,  g_vl);
    cudaGetSymbolAddress((void**)&ath, g_ath); cudaGetSymbolAddress((void**)&atl, g_atl);
    cudaGetSymbolAddress((void**)&uni, g_uni);
    cudaGetSymbolAddress((void**)&pool, g_pool);

    const float scale = powf((float)KHD, -0.25f);
    const int M = BB * LL;

    auto* kProj = gemm_b3<false, true>;
    auto* kF32  = gemm_b3<true,  false>;
    constexpr int SM_TN = 2 * (4 * 128 * 40 * 2);          // 81920
    constexpr int SM_FL = (2*128*136 + 2*4*64*136) * 2;    // 208896
    cudaFuncSetAttribute(kProj, cudaFuncAttributeMaxDynamicSharedMemorySize, SM_TN);
    cudaFuncSetAttribute(kF32,  cudaFuncAttributeMaxDynamicSharedMemorySize, SM_TN);
    cudaFuncSetAttribute(flash_k, cudaFuncAttributeMaxDynamicSharedMemorySize, SM_FL);

    // --- convert inputs ---
    {
        const int nx4 = BB * LL * DD / 4, nw4 = DD * DD / 4;
        split_k<<<(nx4 + 255) / 256, 256>>>(x0, x0h, x0l, nx4);
        split_k<<<(nx4 + 255) / 256, 256>>>(x1, x1h, x1l, nx4);
        split_k<<<(nx4 + 255) / 256, 256>>>(x2, x2h, x2l, nx4);
        split_k<<<(nw4 + 255) / 256, 256>>>(Wk, wkh, wkl, nw4);
        split_k<<<(nw4 + 255) / 256, 256>>>(Wq, wqh, wql, nw4);
        split_k<<<(nw4 + 255) / 256, 256>>>(Wv, wvh, wvl, nw4);
        split_k<<<(nw4 + 255) / 256, 256>>>(Wu, wuh, wul, nw4);
    }

    dim3 blk(256);

    // --- QKV projections ---
    {
        dim3 grid(DD / 128, M / 128);
        kProj<<<grid, blk, SM_TN>>>(x2h, x2l, DD, wkh, wkl, DD,
                                    nullptr, qh, ql, DD, DD, scale, nullptr);
        kProj<<<grid, blk, SM_TN>>>(x1h, x1l, DD, wqh, wql, DD,
                                    nullptr, kh, kl, DD, DD, scale, nullptr);
        kProj<<<grid, blk, SM_TN>>>(x0h, x0l, DD, wvh, wvl, DD,
                                    nullptr, vh, vl, DD, DD, 1.0f, nullptr);
    }

    // --- fused attention ---
    {
        dim3 grid(LL / 128, BB * HH);
        flash_k<<<grid, blk, SM_FL>>>(qh, ql, kh, kl, vh, vl, ath, atl);
    }

    // --- unify ---
    {
        dim3 grid(DD / 128, M / 128);
        kF32<<<grid, blk, SM_TN>>>(ath, atl, DD, wuh, wul, DD,
                                   uni, nullptr, nullptr, DD, DD, 1.0f, bu);
    }

    // --- pool + logits ---
    {
        dim3 grid(DD / 256, BB);
        pool_kernel<<<grid, 256>>>(uni, pool);
    }
    logits_kernel<<<BB, 256>>>(pool, Wmlp, bmlp, out);
}

// round 8
// speedup vs baseline: 5.3456x; 1.3401x over previous
#include <cuda_runtime.h>
#include <cuda_bf16.h>
#include <cuda_fp16.h>
#include <math.h>
#include <stdint.h>

#define BB 16
#define LL 1024
#define DD 1024
#define HH 8
#define KHD 128
#define OUTN 64

typedef __nv_bfloat16  bf16;
typedef __nv_bfloat162 bf162;
typedef __half  h16;
typedef __half2 h162;

// ---------------- scratch (device globals) ----------------
// bf16 split path (pre-softmax precision-critical)
__device__ bf16 g_x1h[BB*LL*DD], g_x1l[BB*LL*DD];
__device__ bf16 g_x2h[BB*LL*DD], g_x2l[BB*LL*DD];
__device__ bf16 g_wkh[DD*DD], g_wkl[DD*DD];
__device__ bf16 g_wqh[DD*DD], g_wql[DD*DD];
__device__ bf16 g_qh[BB*LL*DD], g_ql[BB*LL*DD];
__device__ bf16 g_kh[BB*LL*DD], g_kl[BB*LL*DD];
// fp16 path (post-softmax)
__device__ h16 g_x0h[BB*LL*DD];
__device__ h16 g_wvh[DD*DD], g_wvl[DD*DD];
__device__ h16 g_wuh[DD*DD], g_wul[DD*DD];
__device__ h16 g_vv [BB*LL*DD];
__device__ h16 g_att[BB*LL*DD];
__device__ float g_uni[BB*LL*DD];
__device__ float g_pool[BB*DD];

// ---------------- helpers ----------------
__device__ __forceinline__ void bsplit(float x, bf16& h, bf16& l) {
    h = __float2bfloat16_rn(x);
    l = __float2bfloat16_rn(x - __bfloat162float(h));
}
__device__ __forceinline__ void hsplit(float x, h16& h, h16& l) {
    h = __float2half_rn(x);
    l = __float2half_rn(x - __half2float(h));
}
__device__ __forceinline__ uint32_t pkb(bf16 x, bf16 y) {
    bf162 t; t.x = x; t.y = y; return *(uint32_t*)&t;
}
__device__ __forceinline__ uint32_t pkh(h16 x, h16 y) {
    h162 t; t.x = x; t.y = y; return *(uint32_t*)&t;
}
__device__ __forceinline__ void cpa16(void* s, const void* g) {
    uint32_t sa = (uint32_t)__cvta_generic_to_shared(s);
    asm volatile("cp.async.cg.shared.global [%0], [%1], 16;" :: "r"(sa), "l"(g));
}
__device__ __forceinline__ void cp_commit() {
    asm volatile("cp.async.commit_group;" ::: "memory");
}
__device__ __forceinline__ void cp_wait1() {
    asm volatile("cp.async.wait_group 1;" ::: "memory");
}
__device__ __forceinline__ void ldsm_x4(uint32_t* r, const void* p) {
    uint32_t a = (uint32_t)__cvta_generic_to_shared(p);
    asm volatile("ldmatrix.sync.aligned.m8n8.x4.shared.b16 {%0,%1,%2,%3}, [%4];"
        : "=r"(r[0]), "=r"(r[1]), "=r"(r[2]), "=r"(r[3]) : "r"(a));
}
__device__ __forceinline__ void ldsm_x4t(uint32_t* r, const void* p) {
    uint32_t a = (uint32_t)__cvta_generic_to_shared(p);
    asm volatile("ldmatrix.sync.aligned.m8n8.x4.trans.shared.b16 {%0,%1,%2,%3}, [%4];"
        : "=r"(r[0]), "=r"(r[1]), "=r"(r[2]), "=r"(r[3]) : "r"(a));
}
__device__ __forceinline__ void mma_bf16(float* c, const uint32_t* a, const uint32_t* b) {
    asm volatile(
        "mma.sync.aligned.m16n8k16.row.col.f32.bf16.bf16.f32 "
        "{%0,%1,%2,%3},{%4,%5,%6,%7},{%8,%9},{%0,%1,%2,%3};"
        : "+f"(c[0]), "+f"(c[1]), "+f"(c[2]), "+f"(c[3])
        : "r"(a[0]), "r"(a[1]), "r"(a[2]), "r"(a[3]), "r"(b[0]), "r"(b[1]));
}
__device__ __forceinline__ void mma_f16(float* c, const uint32_t* a, const uint32_t* b) {
    asm volatile(
        "mma.sync.aligned.m16n8k16.row.col.f32.f16.f16.f32 "
        "{%0,%1,%2,%3},{%4,%5,%6,%7},{%8,%9},{%0,%1,%2,%3};"
        : "+f"(c[0]), "+f"(c[1]), "+f"(c[2]), "+f"(c[3])
        : "r"(a[0]), "r"(a[1]), "r"(a[2]), "r"(a[3]), "r"(b[0]), "r"(b[1]));
}

// =================================================================
// bf16 3-MMA TN GEMM (q/k projections). BM=BN=128, BK=32, 256 thr,
// warp tile 64x32, double-buffered cp.async, x4 ldmatrix for A and B.
// C = alpha * A @ B^T, written as split bf16 (hi/lo).
// =================================================================
__global__ void __launch_bounds__(256)
gemm_b3(const bf16* __restrict__ Ah, const bf16* __restrict__ Al,
        const bf16* __restrict__ Bh, const bf16* __restrict__ Bl,
        bf16* __restrict__ Ch, bf16* __restrict__ Cl, float alpha)
{
    extern __shared__ __align__(16) char smem[];
    constexpr int SA  = 128 * 40 * 2;    // bytes per array per stage
    constexpr int STG = 4 * SA;

    const int bm = blockIdx.y * 128, bn = blockIdx.x * 128;
    const int u = threadIdx.x, wid = u >> 5, lane = u & 31;
    const int wm = (wid >> 2) * 64, wn = (wid & 3) * 32;

    float acc[4][4][4];
    #pragma unroll
    for (int i = 0; i < 4; ++i)
        #pragma unroll
        for (int j = 0; j < 4; ++j)
            #pragma unroll
            for (int p = 0; p < 4; ++p) acc[i][j][p] = 0.f;

    auto stage = [&](int buf, int k0) {
        bf16* sAh = (bf16*)(smem + (long)buf * STG);
        bf16* sAl = (bf16*)(smem + (long)buf * STG + SA);
        bf16* sBh = (bf16*)(smem + (long)buf * STG + 2 * SA);
        bf16* sBl = (bf16*)(smem + (long)buf * STG + 3 * SA);
        #pragma unroll
        for (int c = u; c < 512; c += 256) {
            const int row = c >> 2, seg = c & 3;
            const long ga = (long)(bm + row) * DD + k0 + seg * 8;
            const long gb = (long)(bn + row) * DD + k0 + seg * 8;
            cpa16(sAh + row * 40 + seg * 8, Ah + ga);
            cpa16(sAl + row * 40 + seg * 8, Al + ga);
            cpa16(sBh + row * 40 + seg * 8, Bh + gb);
            cpa16(sBl + row * 40 + seg * 8, Bl + gb);
        }
    };

    constexpr int nst = DD / 32;
    stage(0, 0);
    cp_commit();

    // per-lane x4 B address components
    const int brow = ((lane >> 4) & 1) * 8 + (lane & 7);
    const int bcol = ((lane >> 3) & 1) * 8;

    for (int s = 0; s < nst; ++s) {
        if (s + 1 < nst) stage((s + 1) & 1, (s + 1) * 32);
        cp_commit();
        cp_wait1();
        __syncthreads();

        const int buf = s & 1;
        const bf16* sAh = (const bf16*)(smem + (long)buf * STG);
        const bf16* sAl = (const bf16*)(smem + (long)buf * STG + SA);
        const bf16* sBh = (const bf16*)(smem + (long)buf * STG + 2 * SA);
        const bf16* sBl = (const bf16*)(smem + (long)buf * STG + 3 * SA);

        #pragma unroll
        for (int kk = 0; kk < 32; kk += 16) {
            uint32_t ah[4][4], al[4][4];
            #pragma unroll
            for (int mt = 0; mt < 4; ++mt) {
                const int off = (wm + mt * 16 + (lane & 15)) * 40 + kk + (lane >> 4) * 8;
                ldsm_x4(ah[mt], sAh + off);
                ldsm_x4(al[mt], sAl + off);
            }
            #pragma unroll
            for (int np = 0; np < 2; ++np) {
                uint32_t bh4[4], bl4[4];
                const int off = (wn + np * 16 + brow) * 40 + kk + bcol;
                ldsm_x4(bh4, sBh + off);
                ldsm_x4(bl4, sBl + off);
                #pragma unroll
                for (int half = 0; half < 2; ++half) {
                    const int nt = np * 2 + half;
                    const uint32_t* bh = bh4 + half * 2;
                    const uint32_t* bl = bl4 + half * 2;
                    #pragma unroll
                    for (int mt = 0; mt < 4; ++mt) {
                        mma_bf16(acc[mt][nt], ah[mt], bh);
                        mma_bf16(acc[mt][nt], ah[mt], bl);
                        mma_bf16(acc[mt][nt], al[mt], bh);
                    }
                }
            }
        }
        __syncthreads();
    }

    const int tr = lane >> 2, tc = lane & 3;
    #pragma unroll
    for (int mt = 0; mt < 4; ++mt) {
        const int row = bm + wm + mt * 16 + tr;
        #pragma unroll
        for (int nt = 0; nt < 4; ++nt) {
            const int col = bn + wn + nt * 8 + tc * 2;
            const float* c = acc[mt][nt];
            bf16 h0, l0, h1, l1;
            bsplit(c[0] * alpha, h0, l0); bsplit(c[1] * alpha, h1, l1);
            *(uint32_t*)&Ch[(long)row * DD + col] = pkb(h0, h1);
            *(uint32_t*)&Cl[(long)row * DD + col] = pkb(l0, l1);
            bsplit(c[2] * alpha, h0, l0); bsplit(c[3] * alpha, h1, l1);
            *(uint32_t*)&Ch[(long)(row + 8) * DD + col] = pkb(h0, h1);
            *(uint32_t*)&Cl[(long)(row + 8) * DD + col] = pkb(l0, l1);
        }
    }
}

// =================================================================
// fp16 2-MMA TN GEMM: C = A @ B^T  with A single fp16, B split fp16.
// OUT 0: single fp16;  OUT 1: fp32 + bias.
// =================================================================
template<int OUT>
__global__ void __launch_bounds__(256)
gemm_h2(const h16* __restrict__ Ah,
        const h16* __restrict__ Bh, const h16* __restrict__ Bl,
        h16* __restrict__ Chf, float* __restrict__ Cf,
        const float* __restrict__ bias)
{
    extern __shared__ __align__(16) char smem[];
    constexpr int SA  = 128 * 40 * 2;
    constexpr int STG = 3 * SA;

    const int bm = blockIdx.y * 128, bn = blockIdx.x * 128;
    const int u = threadIdx.x, wid = u >> 5, lane = u & 31;
    const int wm = (wid >> 2) * 64, wn = (wid & 3) * 32;

    float acc[4][4][4];
    #pragma unroll
    for (int i = 0; i < 4; ++i)
        #pragma unroll
        for (int j = 0; j < 4; ++j)
            #pragma unroll
            for (int p = 0; p < 4; ++p) acc[i][j][p] = 0.f;

    auto stage = [&](int buf, int k0) {
        h16* sA  = (h16*)(smem + (long)buf * STG);
        h16* sBh = (h16*)(smem + (long)buf * STG + SA);
        h16* sBl = (h16*)(smem + (long)buf * STG + 2 * SA);
        #pragma unroll
        for (int c = u; c < 512; c += 256) {
            const int row = c >> 2, seg = c & 3;
            const long ga = (long)(bm + row) * DD + k0 + seg * 8;
            const long gb = (long)(bn + row) * DD + k0 + seg * 8;
            cpa16(sA  + row * 40 + seg * 8, Ah + ga);
            cpa16(sBh + row * 40 + seg * 8, Bh + gb);
            cpa16(sBl + row * 40 + seg * 8, Bl + gb);
        }
    };

    constexpr int nst = DD / 32;
    stage(0, 0);
    cp_commit();

    const int brow = ((lane >> 4) & 1) * 8 + (lane & 7);
    const int bcol = ((lane >> 3) & 1) * 8;

    for (int s = 0; s < nst; ++s) {
        if (s + 1 < nst) stage((s + 1) & 1, (s + 1) * 32);
        cp_commit();
        cp_wait1();
        __syncthreads();

        const int buf = s & 1;
        const h16* sA  = (const h16*)(smem + (long)buf * STG);
        const h16* sBh = (const h16*)(smem + (long)buf * STG + SA);
        const h16* sBl = (const h16*)(smem + (long)buf * STG + 2 * SA);

        #pragma unroll
        for (int kk = 0; kk < 32; kk += 16) {
            uint32_t ah[4][4];
            #pragma unroll
            for (int mt = 0; mt < 4; ++mt) {
                const int off = (wm + mt * 16 + (lane & 15)) * 40 + kk + (lane >> 4) * 8;
                ldsm_x4(ah[mt], sA + off);
            }
            #pragma unroll
            for (int np = 0; np < 2; ++np) {
                uint32_t bh4[4], bl4[4];
                const int off = (wn + np * 16 + brow) * 40 + kk + bcol;
                ldsm_x4(bh4, sBh + off);
                ldsm_x4(bl4, sBl + off);
                #pragma unroll
                for (int half = 0; half < 2; ++half) {
                    const int nt = np * 2 + half;
                    #pragma unroll
                    for (int mt = 0; mt < 4; ++mt) {
                        mma_f16(acc[mt][nt], ah[mt], bh4 + half * 2);
                        mma_f16(acc[mt][nt], ah[mt], bl4 + half * 2);
                    }
                }
            }
        }
        __syncthreads();
    }

    const int tr = lane >> 2, tc = lane & 3;
    #pragma unroll
    for (int mt = 0; mt < 4; ++mt) {
        const int row = bm + wm + mt * 16 + tr;
        #pragma unroll
        for (int nt = 0; nt < 4; ++nt) {
            const int col = bn + wn + nt * 8 + tc * 2;
            const float* c = acc[mt][nt];
            if (OUT == 0) {
                *(uint32_t*)&Chf[(long)row * DD + col] =
                    pkh(__float2half_rn(c[0]), __float2half_rn(c[1]));
                *(uint32_t*)&Chf[(long)(row + 8) * DD + col] =
                    pkh(__float2half_rn(c[2]), __float2half_rn(c[3]));
            } else {
                const float b0 = __ldg(bias + col), b1 = __ldg(bias + col + 1);
                *(float2*)&Cf[(long)row * DD + col]       = make_float2(c[0] + b0, c[1] + b1);
                *(float2*)&Cf[(long)(row + 8) * DD + col] = make_float2(c[2] + b0, c[3] + b1);
            }
        }
    }
}

// =================================================================
// Fused flash attention: QK^T bf16 3-MMA, online softmax, P fp16
// single, V fp16 single -> PV 1 MMA. att out single fp16.
// =================================================================
__global__ void __launch_bounds__(256)
flash_k(const bf16* __restrict__ Qh, const bf16* __restrict__ Ql,
        const bf16* __restrict__ Kh, const bf16* __restrict__ Kl,
        const h16* __restrict__ V, h16* __restrict__ O_)
{
    extern __shared__ __align__(16) char sm[];
    constexpr int QS = 128 * 136;   // elems per Q array
    constexpr int TS = 64 * 136;    // elems per KV array per stage
    bf16* sQh = (bf16*)sm;
    bf16* sQl = sQh + QS;
    char* sT  = (char*)(sQl + QS);  // per stage: Kh(bf16), Kl(bf16), V(h16)
    constexpr long STG = 3L * TS * 2;

    const int bh = blockIdx.y, b = bh >> 3, h = bh & 7;
    const int q0 = blockIdx.x * 128;
    const int u = threadIdx.x, wid = u >> 5, lane = u & 31;
    const int tr = lane >> 2, tc = lane & 3;

    const long qg = ((long)b * LL + q0) * DD + h * KHD;
    const long kg = (long)b * LL * DD + h * KHD;

    for (int c = u; c < 2048; c += 256) {
        const int r = c >> 4, s = (c & 15) * 8;
        cpa16(sQh + r * 136 + s, Qh + qg + (long)r * DD + s);
        cpa16(sQl + r * 136 + s, Ql + qg + (long)r * DD + s);
    }
    auto stage = [&](int buf, int kv0) {
        bf16* pKh = (bf16*)(sT + buf * STG);
        bf16* pKl = pKh + TS;
        h16*  pV  = (h16*)(pKl + TS);
        for (int c = u; c < 1024; c += 256) {
            const int r = c >> 4, s = (c & 15) * 8;
            const long g = kg + (long)(kv0 + r) * DD + s;
            cpa16(pKh + r * 136 + s, Kh + g);
            cpa16(pKl + r * 136 + s, Kl + g);
            cpa16(pV  + r * 136 + s, V + g);
        }
    };
    stage(0, 0);
    cp_commit();

    float O[16][4];
    #pragma unroll
    for (int i = 0; i < 16; ++i)
        #pragma unroll
        for (int j = 0; j < 4; ++j) O[i][j] = 0.f;
    float m0 = -1e30f, m1 = -1e30f, l0 = 0.f, l1 = 0.f;

    // lane components for x4 loads
    const int brow = ((lane >> 4) & 1) * 8 + (lane & 7);   // K x4 rows
    const int bcol = ((lane >> 3) & 1) * 8;                // K x4 k-col
    const int vrow = ((lane >> 3) & 1) * 8 + (lane & 7);   // V x4t k-rows
    const int vsel = (lane >> 4);                          // V x4t d-col select

    for (int t = 0; t < 16; ++t) {
        if (t + 1 < 16) stage((t + 1) & 1, (t + 1) * 64);
        cp_commit();
        cp_wait1();
        __syncthreads();

        const bf16* cKh = (const bf16*)(sT + (t & 1) * STG);
        const bf16* cKl = cKh + TS;
        const h16*  cV  = (const h16*)(cKl + TS);

        // ---- S = Q K^T (bf16 3-MMA) ----
        float S[8][4];
        #pragma unroll
        for (int i = 0; i < 8; ++i)
            #pragma unroll
            for (int j = 0; j < 4; ++j) S[i][j] = 0.f;

        #pragma unroll
        for (int kk = 0; kk < 128; kk += 16) {
            uint32_t ah[4], al[4];
            const int aoff = (wid * 16 + (lane & 15)) * 136 + kk + (lane >> 4) * 8;
            ldsm_x4(ah, sQh + aoff);
            ldsm_x4(al, sQl + aoff);
            #pragma unroll
            for (int np = 0; np < 4; ++np) {
                uint32_t bh4[4], bl4[4];
                const int boff = (np * 16 + brow) * 136 + kk + bcol;
                ldsm_x4(bh4, cKh + boff);
                ldsm_x4(bl4, cKl + boff);
                #pragma unroll
                for (int half = 0; half < 2; ++half) {
                    float* s_ = S[np * 2 + half];
                    mma_bf16(s_, ah, bh4 + half * 2);
                    mma_bf16(s_, ah, bl4 + half * 2);
                    mma_bf16(s_, al, bh4 + half * 2);
                }
            }
        }

        // ---- online softmax ----
        float rm0 = -1e30f, rm1 = -1e30f;
        #pragma unroll
        for (int nt = 0; nt < 8; ++nt) {
            rm0 = fmaxf(rm0, fmaxf(S[nt][0], S[nt][1]));
            rm1 = fmaxf(rm1, fmaxf(S[nt][2], S[nt][3]));
        }
        rm0 = fmaxf(rm0, __shfl_xor_sync(~0u, rm0, 1));
        rm0 = fmaxf(rm0, __shfl_xor_sync(~0u, rm0, 2));
        rm1 = fmaxf(rm1, __shfl_xor_sync(~0u, rm1, 1));
        rm1 = fmaxf(rm1, __shfl_xor_sync(~0u, rm1, 2));
        const float M0 = fmaxf(m0, rm0), M1 = fmaxf(m1, rm1);
        const float f0 = __expf(m0 - M0), f1 = __expf(m1 - M1);
        m0 = M0; m1 = M1;
        l0 *= f0; l1 *= f1;
        #pragma unroll
        for (int dt = 0; dt < 16; ++dt) {
            O[dt][0] *= f0; O[dt][1] *= f0;
            O[dt][2] *= f1; O[dt][3] *= f1;
        }

        // ---- P = exp(S-M) fp16 single; PV 1-MMA ----
        #pragma unroll
        for (int kc = 0; kc < 4; ++kc) {
            uint32_t pa[4];
            #pragma unroll
            for (int half = 0; half < 2; ++half) {
                const int nt = kc * 2 + half;
                const float p0 = __expf(S[nt][0] - M0);
                const float p1 = __expf(S[nt][1] - M0);
                const float p2 = __expf(S[nt][2] - M1);
                const float p3 = __expf(S[nt][3] - M1);
                l0 += p0 + p1; l1 += p2 + p3;
                pa[half ? 2 : 0] = pkh(__float2half_rn(p0), __float2half_rn(p1));
                pa[half ? 3 : 1] = pkh(__float2half_rn(p2), __float2half_rn(p3));
            }
            #pragma unroll
            for (int dt = 0; dt < 16; dt += 2) {
                uint32_t bv[4];
                const int voff = (kc * 16 + vrow) * 136 + (dt + vsel) * 8;
                ldsm_x4t(bv, cV + voff);
                mma_f16(O[dt],     pa, bv);
                mma_f16(O[dt + 1], pa, bv + 2);
            }
        }
        __syncthreads();
    }

    l0 += __shfl_xor_sync(~0u, l0, 1); l0 += __shfl_xor_sync(~0u, l0, 2);
    l1 += __shfl_xor_sync(~0u, l1, 1); l1 += __shfl_xor_sync(~0u, l1, 2);
    const float i0 = 1.f / l0, i1 = 1.f / l1;
    const long og = ((long)b * LL + q0 + wid * 16) * DD + h * KHD;
    #pragma unroll
    for (int dt = 0; dt < 16; ++dt) {
        const int col = dt * 8 + tc * 2;
        *(uint32_t*)&O_[og + (long)tr * DD + col] =
            pkh(__float2half_rn(O[dt][0] * i0), __float2half_rn(O[dt][1] * i0));
        *(uint32_t*)&O_[og + (long)(tr + 8) * DD + col] =
            pkh(__float2half_rn(O[dt][2] * i1), __float2half_rn(O[dt][3] * i1));
    }
}

// ---------------- converts ----------------
__global__ void split_b(const float* __restrict__ in, bf16* __restrict__ hi,
                        bf16* __restrict__ lo, int n4)
{
    const int i = blockIdx.x * 256 + threadIdx.x;
    if (i >= n4) return;
    const float4 v = ((const float4*)in)[i];
    bf16 h0, l0, h1, l1, h2, l2, h3, l3;
    bsplit(v.x, h0, l0); bsplit(v.y, h1, l1);
    bsplit(v.z, h2, l2); bsplit(v.w, h3, l3);
    ((uint32_t*)hi)[i * 2]     = pkb(h0, h1);
    ((uint32_t*)hi)[i * 2 + 1] = pkb(h2, h3);
    ((uint32_t*)lo)[i * 2]     = pkb(l0, l1);
    ((uint32_t*)lo)[i * 2 + 1] = pkb(l2, l3);
}
__global__ void split_h(const float* __restrict__ in, h16* __restrict__ hi,
                        h16* __restrict__ lo, int n4)
{
    const int i = blockIdx.x * 256 + threadIdx.x;
    if (i >= n4) return;
    const float4 v = ((const float4*)in)[i];
    h16 h0, l0, h1, l1, h2, l2, h3, l3;
    hsplit(v.x, h0, l0); hsplit(v.y, h1, l1);
    hsplit(v.z, h2, l2); hsplit(v.w, h3, l3);
    ((uint32_t*)hi)[i * 2]     = pkh(h0, h1);
    ((uint32_t*)hi)[i * 2 + 1] = pkh(h2, h3);
    if (lo) {
        ((uint32_t*)lo)[i * 2]     = pkh(l0, l1);
        ((uint32_t*)lo)[i * 2 + 1] = pkh(l2, l3);
    }
}

// ---------------- pool + logits ----------------
__global__ void pool_kernel(const float* __restrict__ uni, float* __restrict__ pool)
{
    const int n = blockIdx.x * 256 + threadIdx.x;
    const int b = blockIdx.y;
    const float* p = uni + (long)b * LL * DD + n;
    float s = 0.f, m = -1e30f;
    for (int l = 0; l < LL; ++l) {
        float v = p[(long)l * DD];
        s += v;
        m = fmaxf(m, v);
    }
    pool[b * DD + n] = s * (1.f / LL) + m;
}

__global__ void logits_kernel(const float* __restrict__ pool,
                              const float* __restrict__ Wm,
                              const float* __restrict__ bm,
                              float* __restrict__ out)
{
    const int b = blockIdx.x;
    __shared__ float ps[DD];
    for (int i = threadIdx.x; i < DD; i += blockDim.x) ps[i] = pool[b * DD + i];
    __syncthreads();
    const int o = threadIdx.x;
    if (o < OUTN) {
        float s = bm[o];
        const float* w = Wm + (long)o * DD;
        for (int kk = 0; kk < DD; ++kk) s += ps[kk] * w[kk];
        out[b * OUTN + o] = s;
    }
}

// =================================================================
extern "C" void kernel_launch(void* const* d_in, const int* in_sizes, int n_in,
                              void* d_out, int out_size)
{
    const float* x0   = (const float*)d_in[0];
    const float* x1   = (const float*)d_in[1];
    const float* x2   = (const float*)d_in[2];
    const float* Wk   = (const float*)d_in[5];
    const float* Wq   = (const float*)d_in[6];
    const float* Wv   = (const float*)d_in[7];
    const float* Wu   = (const float*)d_in[8];
    const float* bu   = (const float*)d_in[9];
    const float* Wmlp = (const float*)d_in[10];
    const float* bmlp = (const float*)d_in[11];
    float* out = (float*)d_out;

    bf16 *x1h,*x1l,*x2h,*x2l,*wkh,*wkl,*wqh,*wql,*qh,*ql,*kh,*kl;
    h16  *x0h,*wvh,*wvl,*wuh,*wul,*vv,*att;
    float *uni,*pool;
    cudaGetSymbolAddress((void**)&x1h, g_x1h); cudaGetSymbolAddress((void**)&x1l, g_x1l);
    cudaGetSymbolAddress((void**)&x2h, g_x2h); cudaGetSymbolAddress((void**)&x2l, g_x2l);
    cudaGetSymbolAddress((void**)&wkh, g_wkh); cudaGetSymbolAddress((void**)&wkl, g_wkl);
    cudaGetSymbolAddress((void**)&wqh, g_wqh); cudaGetSymbolAddress((void**)&wql, g_wql);
    cudaGetSymbolAddress((void**)&qh,  g_qh);  cudaGetSymbolAddress((void**)&ql,  g_ql);
    cudaGetSymbolAddress((void**)&kh,  g_kh);  cudaGetSymbolAddress((void**)&kl,  g_kl);
    cudaGetSymbolAddress((void**)&x0h, g_x0h);
    cudaGetSymbolAddress((void**)&wvh, g_wvh); cudaGetSymbolAddress((void**)&wvl, g_wvl);
    cudaGetSymbolAddress((void**)&wuh, g_wuh); cudaGetSymbolAddress((void**)&wul, g_wul);
    cudaGetSymbolAddress((void**)&vv,  g_vv);  cudaGetSymbolAddress((void**)&att, g_att);
    cudaGetSymbolAddress((void**)&uni, g_uni);
    cudaGetSymbolAddress((void**)&pool, g_pool);

    const float scale = powf((float)KHD, -0.25f);
    const int M = BB * LL;

    constexpr int SM_B3 = 2 * (4 * 128 * 40 * 2);                 // 81920
    constexpr int SM_H2 = 2 * (3 * 128 * 40 * 2);                 // 61440
    constexpr int SM_FL = 2*128*136*2 + 2*3*64*136*2;             // 174080
    cudaFuncSetAttribute(gemm_b3,   cudaFuncAttributeMaxDynamicSharedMemorySize, SM_B3);
    cudaFuncSetAttribute(gemm_h2<0>,cudaFuncAttributeMaxDynamicSharedMemorySize, SM_H2);
    cudaFuncSetAttribute(gemm_h2<1>,cudaFuncAttributeMaxDynamicSharedMemorySize, SM_H2);
    cudaFuncSetAttribute(flash_k,   cudaFuncAttributeMaxDynamicSharedMemorySize, SM_FL);

    // --- convert inputs ---
    {
        const int nx4 = BB * LL * DD / 4, nw4 = DD * DD / 4;
        split_b<<<(nx4 + 255) / 256, 256>>>(x1, x1h, x1l, nx4);
        split_b<<<(nx4 + 255) / 256, 256>>>(x2, x2h, x2l, nx4);
        split_b<<<(nw4 + 255) / 256, 256>>>(Wk, wkh, wkl, nw4);
        split_b<<<(nw4 + 255) / 256, 256>>>(Wq, wqh, wql, nw4);
        split_h<<<(nx4 + 255) / 256, 256>>>(x0, x0h, nullptr, nx4);
        split_h<<<(nw4 + 255) / 256, 256>>>(Wv, wvh, wvl, nw4);
        split_h<<<(nw4 + 255) / 256, 256>>>(Wu, wuh, wul, nw4);
    }

    dim3 blk(256);
    dim3 gproj(DD / 128, M / 128);

    // --- projections ---
    gemm_b3<<<gproj, blk, SM_B3>>>(x2h, x2l, wkh, wkl, qh, ql, scale);  // q
    gemm_b3<<<gproj, blk, SM_B3>>>(x1h, x1l, wqh, wql, kh, kl, scale);  // k
    gemm_h2<0><<<gproj, blk, SM_H2>>>(x0h, wvh, wvl, vv, nullptr, nullptr); // v

    // --- fused attention ---
    {
        dim3 grid(LL / 128, BB * HH);
        flash_k<<<grid, blk, SM_FL>>>(qh, ql, kh, kl, vv, att);
    }

    // --- unify ---
    gemm_h2<1><<<gproj, blk, SM_H2>>>(att, wuh, wul, nullptr, uni, bu);

    // --- pool + logits ---
    {
        dim3 grid(DD / 256, BB);
        pool_kernel<<<grid, 256>>>(uni, pool);
    }
    logits_kernel<<<BB, 256>>>(pool, Wmlp, bmlp, out);
}

// round 9
// speedup vs baseline: 5.6801x; 1.0626x over previous
#include <cuda_runtime.h>
#include <cuda_bf16.h>
#include <cuda_fp16.h>
#include <math.h>
#include <stdint.h>

#define BB 16
#define LL 1024
#define DD 1024
#define HH 8
#define KHD 128
#define OUTN 64

typedef __nv_bfloat16  bf16;
typedef __nv_bfloat162 bf162;
typedef __half  h16;
typedef __half2 h162;

// ---------------- scratch ----------------
__device__ bf16 g_x1h[BB*LL*DD], g_x1l[BB*LL*DD];
__device__ bf16 g_x2h[BB*LL*DD], g_x2l[BB*LL*DD];
__device__ bf16 g_wkh[DD*DD], g_wkl[DD*DD];
__device__ bf16 g_wqh[DD*DD], g_wql[DD*DD];
__device__ bf16 g_qh[BB*LL*DD], g_ql[BB*LL*DD];
__device__ bf16 g_kh[BB*LL*DD], g_kl[BB*LL*DD];
__device__ h16 g_x0h[BB*LL*DD];
__device__ h16 g_wvh[DD*DD];
__device__ h16 g_wuh[DD*DD], g_wul[DD*DD];
__device__ h16 g_vv [BB*LL*DD];
__device__ h16 g_att[BB*LL*DD];
__device__ float    g_psum[BB*DD];
__device__ unsigned g_pmax[BB*DD];

// ---------------- helpers ----------------
__device__ __forceinline__ void bsplit(float x, bf16& h, bf16& l) {
    h = __float2bfloat16_rn(x);
    l = __float2bfloat16_rn(x - __bfloat162float(h));
}
__device__ __forceinline__ void hsplit(float x, h16& h, h16& l) {
    h = __float2half_rn(x);
    l = __float2half_rn(x - __half2float(h));
}
__device__ __forceinline__ uint32_t pkb(bf16 x, bf16 y) {
    bf162 t; t.x = x; t.y = y; return *(uint32_t*)&t;
}
__device__ __forceinline__ uint32_t pkh(h16 x, h16 y) {
    h162 t; t.x = x; t.y = y; return *(uint32_t*)&t;
}
__device__ __forceinline__ void cpa16(void* s, const void* g) {
    uint32_t sa = (uint32_t)__cvta_generic_to_shared(s);
    asm volatile("cp.async.cg.shared.global [%0], [%1], 16;" :: "r"(sa), "l"(g));
}
__device__ __forceinline__ void cp_commit() {
    asm volatile("cp.async.commit_group;" ::: "memory");
}
__device__ __forceinline__ void cp_wait1() {
    asm volatile("cp.async.wait_group 1;" ::: "memory");
}
__device__ __forceinline__ void cp_wait2() {
    asm volatile("cp.async.wait_group 2;" ::: "memory");
}
__device__ __forceinline__ void ldsm_x4(uint32_t* r, const void* p) {
    uint32_t a = (uint32_t)__cvta_generic_to_shared(p);
    asm volatile("ldmatrix.sync.aligned.m8n8.x4.shared.b16 {%0,%1,%2,%3}, [%4];"
        : "=r"(r[0]), "=r"(r[1]), "=r"(r[2]), "=r"(r[3]) : "r"(a));
}
__device__ __forceinline__ void ldsm_x4t(uint32_t* r, const void* p) {
    uint32_t a = (uint32_t)__cvta_generic_to_shared(p);
    asm volatile("ldmatrix.sync.aligned.m8n8.x4.trans.shared.b16 {%0,%1,%2,%3}, [%4];"
        : "=r"(r[0]), "=r"(r[1]), "=r"(r[2]), "=r"(r[3]) : "r"(a));
}
__device__ __forceinline__ void mma_bf16(float* c, const uint32_t* a, const uint32_t* b) {
    asm volatile(
        "mma.sync.aligned.m16n8k16.row.col.f32.bf16.bf16.f32 "
        "{%0,%1,%2,%3},{%4,%5,%6,%7},{%8,%9},{%0,%1,%2,%3};"
        : "+f"(c[0]), "+f"(c[1]), "+f"(c[2]), "+f"(c[3])
        : "r"(a[0]), "r"(a[1]), "r"(a[2]), "r"(a[3]), "r"(b[0]), "r"(b[1]));
}
__device__ __forceinline__ void mma_f16(float* c, const uint32_t* a, const uint32_t* b) {
    asm volatile(
        "mma.sync.aligned.m16n8k16.row.col.f32.f16.f16.f32 "
        "{%0,%1,%2,%3},{%4,%5,%6,%7},{%8,%9},{%0,%1,%2,%3};"
        : "+f"(c[0]), "+f"(c[1]), "+f"(c[2]), "+f"(c[3])
        : "r"(a[0]), "r"(a[1]), "r"(a[2]), "r"(a[3]), "r"(b[0]), "r"(b[1]));
}
__device__ __forceinline__ unsigned fkey(float v) {
    unsigned u = __float_as_uint(v);
    return (u & 0x80000000u) ? ~u : (u | 0x80000000u);
}
__device__ __forceinline__ float fdec(unsigned k) {
    unsigned u = (k & 0x80000000u) ? (k ^ 0x80000000u) : ~k;
    return __uint_as_float(u);
}

// =================================================================
// bf16 3-MMA TN GEMM (q/k proj). BM=BN=128, BK=16, 4-stage cp.async,
// stride-24 smem rows, 256 thr, warp tile 64x32, 2 CTA/SM.
// C = alpha * A @ B^T, split-bf16 out.
// =================================================================
__global__ void __launch_bounds__(256, 2)
gemm_b3(const bf16* __restrict__ Ah, const bf16* __restrict__ Al,
        const bf16* __restrict__ Bh, const bf16* __restrict__ Bl,
        bf16* __restrict__ Ch, bf16* __restrict__ Cl, float alpha)
{
    extern __shared__ __align__(16) char smem[];
    constexpr int RS  = 24;          // elems per row
    constexpr int ARR = 128 * RS;    // elems per array
    constexpr int STG = 4 * ARR;     // elems per stage (Ah,Al,Bh,Bl)

    const int bm = blockIdx.y * 128, bn = blockIdx.x * 128;
    const int u = threadIdx.x, wid = u >> 5, lane = u & 31;
    const int wm = (wid >> 2) * 64, wn = (wid & 3) * 32;

    float acc[4][4][4];
    #pragma unroll
    for (int i = 0; i < 4; ++i)
        #pragma unroll
        for (int j = 0; j < 4; ++j)
            #pragma unroll
            for (int p = 0; p < 4; ++p) acc[i][j][p] = 0.f;

    const int srow = u >> 1, shalf = (u & 1) * 8;
    auto stage = [&](int buf, int k0) {
        bf16* s0 = (bf16*)smem + (long)buf * STG + srow * RS + shalf;
        const long ga = (long)(bm + srow) * DD + k0 + shalf;
        const long gb = (long)(bn + srow) * DD + k0 + shalf;
        cpa16(s0,           Ah + ga);
        cpa16(s0 + ARR,     Al + ga);
        cpa16(s0 + 2 * ARR, Bh + gb);
        cpa16(s0 + 3 * ARR, Bl + gb);
    };

    constexpr int nst = DD / 16;   // 64
    #pragma unroll
    for (int t = 0; t < 3; ++t) { stage(t, t * 16); cp_commit(); }

    const int arow = lane & 15, asel = (lane >> 4) * 8;
    const int brow = ((lane >> 4) & 1) * 8 + (lane & 7);
    const int bcol = ((lane >> 3) & 1) * 8;

    for (int s = 0; s < nst; ++s) {
        cp_wait2();
        __syncthreads();
        if (s + 3 < nst) stage((s + 3) & 3, (s + 3) * 16);
        cp_commit();

        const bf16* base = (const bf16*)smem + (long)(s & 3) * STG;
        const bf16* sAh = base;
        const bf16* sAl = base + ARR;
        const bf16* sBh = base + 2 * ARR;
        const bf16* sBl = base + 3 * ARR;

        uint32_t ah[4][4], al[4][4];
        #pragma unroll
        for (int mt = 0; mt < 4; ++mt) {
            const int off = (wm + mt * 16 + arow) * RS + asel;
            ldsm_x4(ah[mt], sAh + off);
            ldsm_x4(al[mt], sAl + off);
        }
        #pragma unroll
        for (int np = 0; np < 2; ++np) {
            uint32_t bh4[4], bl4[4];
            const int off = (wn + np * 16 + brow) * RS + bcol;
            ldsm_x4(bh4, sBh + off);
            ldsm_x4(bl4, sBl + off);
            #pragma unroll
            for (int half = 0; half < 2; ++half) {
                const int nt = np * 2 + half;
                #pragma unroll
                for (int mt = 0; mt < 4; ++mt) {
                    mma_bf16(acc[mt][nt], ah[mt], bh4 + half * 2);
                    mma_bf16(acc[mt][nt], ah[mt], bl4 + half * 2);
                    mma_bf16(acc[mt][nt], al[mt], bh4 + half * 2);
                }
            }
        }
    }

    const int tr = lane >> 2, tc = lane & 3;
    #pragma unroll
    for (int mt = 0; mt < 4; ++mt) {
        const int row = bm + wm + mt * 16 + tr;
        #pragma unroll
        for (int nt = 0; nt < 4; ++nt) {
            const int col = bn + wn + nt * 8 + tc * 2;
            const float* c = acc[mt][nt];
            bf16 h0, l0, h1, l1;
            bsplit(c[0] * alpha, h0, l0); bsplit(c[1] * alpha, h1, l1);
            *(uint32_t*)&Ch[(long)row * DD + col] = pkb(h0, h1);
            *(uint32_t*)&Cl[(long)row * DD + col] = pkb(l0, l1);
            bsplit(c[2] * alpha, h0, l0); bsplit(c[3] * alpha, h1, l1);
            *(uint32_t*)&Ch[(long)(row + 8) * DD + col] = pkb(h0, h1);
            *(uint32_t*)&Cl[(long)(row + 8) * DD + col] = pkb(l0, l1);
        }
    }
}

// =================================================================
// fp16 TN GEMM, NMMA terms (B split if 2). 4-stage BK=16.
// POOL 0: write fp16 C;  POOL 1: fused mean/max pooling (no C write).
// =================================================================
template<int NMMA, int POOL>
__global__ void __launch_bounds__(256, 2)
gemm_h(const h16* __restrict__ Ax,
       const h16* __restrict__ Bh, const h16* __restrict__ Bl,
       h16* __restrict__ Chf, const float* __restrict__ bias,
       float* __restrict__ psum, unsigned* __restrict__ pmax)
{
    extern __shared__ __align__(16) char smem[];
    constexpr int RS  = 24;
    constexpr int ARR = 128 * RS;
    constexpr int NAR = 1 + NMMA;
    constexpr int STG = NAR * ARR;

    const int bm = blockIdx.y * 128, bn = blockIdx.x * 128;
    const int u = threadIdx.x, wid = u >> 5, lane = u & 31;
    const int wm = (wid >> 2) * 64, wn = (wid & 3) * 32;

    float acc[4][4][4];
    #pragma unroll
    for (int i = 0; i < 4; ++i)
        #pragma unroll
        for (int j = 0; j < 4; ++j)
            #pragma unroll
            for (int p = 0; p < 4; ++p) acc[i][j][p] = 0.f;

    const int srow = u >> 1, shalf = (u & 1) * 8;
    auto stage = [&](int buf, int k0) {
        h16* s0 = (h16*)smem + (long)buf * STG + srow * RS + shalf;
        const long ga = (long)(bm + srow) * DD + k0 + shalf;
        const long gb = (long)(bn + srow) * DD + k0 + shalf;
        cpa16(s0,       Ax + ga);
        cpa16(s0 + ARR, Bh + gb);
        if (NMMA == 2) cpa16(s0 + 2 * ARR, Bl + gb);
    };

    constexpr int nst = DD / 16;
    #pragma unroll
    for (int t = 0; t < 3; ++t) { stage(t, t * 16); cp_commit(); }

    const int arow = lane & 15, asel = (lane >> 4) * 8;
    const int brow = ((lane >> 4) & 1) * 8 + (lane & 7);
    const int bcol = ((lane >> 3) & 1) * 8;

    for (int s = 0; s < nst; ++s) {
        cp_wait2();
        __syncthreads();
        if (s + 3 < nst) stage((s + 3) & 3, (s + 3) * 16);
        cp_commit();

        const h16* base = (const h16*)smem + (long)(s & 3) * STG;
        const h16* sA  = base;
        const h16* sBh = base + ARR;
        const h16* sBl = base + 2 * ARR;

        uint32_t ah[4][4];
        #pragma unroll
        for (int mt = 0; mt < 4; ++mt)
            ldsm_x4(ah[mt], sA + (wm + mt * 16 + arow) * RS + asel);
        #pragma unroll
        for (int np = 0; np < 2; ++np) {
            uint32_t bh4[4], bl4[4];
            const int off = (wn + np * 16 + brow) * RS + bcol;
            ldsm_x4(bh4, sBh + off);
            if (NMMA == 2) ldsm_x4(bl4, sBl + off);
            #pragma unroll
            for (int half = 0; half < 2; ++half) {
                const int nt = np * 2 + half;
                #pragma unroll
                for (int mt = 0; mt < 4; ++mt) {
                    mma_f16(acc[mt][nt], ah[mt], bh4 + half * 2);
                    if (NMMA == 2) mma_f16(acc[mt][nt], ah[mt], bl4 + half * 2);
                }
            }
        }
    }

    const int tr = lane >> 2, tc = lane & 3;
    if (POOL == 0) {
        #pragma unroll
        for (int mt = 0; mt < 4; ++mt) {
            const int row = bm + wm + mt * 16 + tr;
            #pragma unroll
            for (int nt = 0; nt < 4; ++nt) {
                const int col = bn + wn + nt * 8 + tc * 2;
                const float* c = acc[mt][nt];
                *(uint32_t*)&Chf[(long)row * DD + col] =
                    pkh(__float2half_rn(c[0]), __float2half_rn(c[1]));
                *(uint32_t*)&Chf[(long)(row + 8) * DD + col] =
                    pkh(__float2half_rn(c[2]), __float2half_rn(c[3]));
            }
        }
    } else {
        // fused pooling: per-column sum & max over this CTA's 128 rows
        const int b = bm >> 10;
        float sum[4][2], mx[4][2];
        #pragma unroll
        for (int nt = 0; nt < 4; ++nt) {
            #pragma unroll
            for (int j = 0; j < 2; ++j) {
                const int col = bn + wn + nt * 8 + tc * 2 + j;
                const float bv = __ldg(bias + col);
                float s_ = 0.f, m_ = -1e30f;
                #pragma unroll
                for (int mt = 0; mt < 4; ++mt) {
                    const float v0 = acc[mt][nt][j] + bv;
                    const float v1 = acc[mt][nt][j + 2] + bv;
                    s_ += v0 + v1;
                    m_ = fmaxf(m_, fmaxf(v0, v1));
                }
                sum[nt][j] = s_; mx[nt][j] = m_;
            }
        }
        #pragma unroll
        for (int o = 4; o <= 16; o <<= 1) {
            #pragma unroll
            for (int nt = 0; nt < 4; ++nt)
                #pragma unroll
                for (int j = 0; j < 2; ++j) {
                    sum[nt][j] += __shfl_xor_sync(~0u, sum[nt][j], o);
                    mx[nt][j] = fmaxf(mx[nt][j], __shfl_xor_sync(~0u, mx[nt][j], o));
                }
        }
        if (tr == 0) {
            #pragma unroll
            for (int nt = 0; nt < 4; ++nt)
                #pragma unroll
                for (int j = 0; j < 2; ++j) {
                    const int col = bn + wn + nt * 8 + tc * 2 + j;
                    atomicAdd(&psum[b * DD + col], sum[nt][j]);
                    atomicMax(&pmax[b * DD + col], fkey(mx[nt][j]));
                }
        }
    }
}

// =================================================================
// Fused flash attention (unchanged from R8).
// =================================================================
__global__ void __launch_bounds__(256)
flash_k(const bf16* __restrict__ Qh, const bf16* __restrict__ Ql,
        const bf16* __restrict__ Kh, const bf16* __restrict__ Kl,
        const h16* __restrict__ V, h16* __restrict__ O_)
{
    extern __shared__ __align__(16) char sm[];
    constexpr int QS = 128 * 136;
    constexpr int TS = 64 * 136;
    bf16* sQh = (bf16*)sm;
    bf16* sQl = sQh + QS;
    char* sT  = (char*)(sQl + QS);
    constexpr long STG = 3L * TS * 2;

    const int bh = blockIdx.y, b = bh >> 3, h = bh & 7;
    const int q0 = blockIdx.x * 128;
    const int u = threadIdx.x, wid = u >> 5, lane = u & 31;
    const int tr = lane >> 2, tc = lane & 3;

    const long qg = ((long)b * LL + q0) * DD + h * KHD;
    const long kg = (long)b * LL * DD + h * KHD;

    for (int c = u; c < 2048; c += 256) {
        const int r = c >> 4, s = (c & 15) * 8;
        cpa16(sQh + r * 136 + s, Qh + qg + (long)r * DD + s);
        cpa16(sQl + r * 136 + s, Ql + qg + (long)r * DD + s);
    }
    auto stage = [&](int buf, int kv0) {
        bf16* pKh = (bf16*)(sT + buf * STG);
        bf16* pKl = pKh + TS;
        h16*  pV  = (h16*)(pKl + TS);
        for (int c = u; c < 1024; c += 256) {
            const int r = c >> 4, s = (c & 15) * 8;
            const long g = kg + (long)(kv0 + r) * DD + s;
            cpa16(pKh + r * 136 + s, Kh + g);
            cpa16(pKl + r * 136 + s, Kl + g);
            cpa16(pV  + r * 136 + s, V + g);
        }
    };
    stage(0, 0);
    cp_commit();

    float O[16][4];
    #pragma unroll
    for (int i = 0; i < 16; ++i)
        #pragma unroll
        for (int j = 0; j < 4; ++j) O[i][j] = 0.f;
    float m0 = -1e30f, m1 = -1e30f, l0 = 0.f, l1 = 0.f;

    const int brow = ((lane >> 4) & 1) * 8 + (lane & 7);
    const int bcol = ((lane >> 3) & 1) * 8;
    const int vrow = ((lane >> 3) & 1) * 8 + (lane & 7);
    const int vsel = (lane >> 4);

    for (int t = 0; t < 16; ++t) {
        if (t + 1 < 16) stage((t + 1) & 1, (t + 1) * 64);
        cp_commit();
        cp_wait1();
        __syncthreads();

        const bf16* cKh = (const bf16*)(sT + (t & 1) * STG);
        const bf16* cKl = cKh + TS;
        const h16*  cV  = (const h16*)(cKl + TS);

        float S[8][4];
        #pragma unroll
        for (int i = 0; i < 8; ++i)
            #pragma unroll
            for (int j = 0; j < 4; ++j) S[i][j] = 0.f;

        #pragma unroll
        for (int kk = 0; kk < 128; kk += 16) {
            uint32_t ah[4], al[4];
            const int aoff = (wid * 16 + (lane & 15)) * 136 + kk + (lane >> 4) * 8;
            ldsm_x4(ah, sQh + aoff);
            ldsm_x4(al, sQl + aoff);
            #pragma unroll
            for (int np = 0; np < 4; ++np) {
                uint32_t bh4[4], bl4[4];
                const int boff = (np * 16 + brow) * 136 + kk + bcol;
                ldsm_x4(bh4, cKh + boff);
                ldsm_x4(bl4, cKl + boff);
                #pragma unroll
                for (int half = 0; half < 2; ++half) {
                    float* s_ = S[np * 2 + half];
                    mma_bf16(s_, ah, bh4 + half * 2);
                    mma_bf16(s_, ah, bl4 + half * 2);
                    mma_bf16(s_, al, bh4 + half * 2);
                }
            }
        }

        float rm0 = -1e30f, rm1 = -1e30f;
        #pragma unroll
        for (int nt = 0; nt < 8; ++nt) {
            rm0 = fmaxf(rm0, fmaxf(S[nt][0], S[nt][1]));
            rm1 = fmaxf(rm1, fmaxf(S[nt][2], S[nt][3]));
        }
        rm0 = fmaxf(rm0, __shfl_xor_sync(~0u, rm0, 1));
        rm0 = fmaxf(rm0, __shfl_xor_sync(~0u, rm0, 2));
        rm1 = fmaxf(rm1, __shfl_xor_sync(~0u, rm1, 1));
        rm1 = fmaxf(rm1, __shfl_xor_sync(~0u, rm1, 2));
        const float M0 = fmaxf(m0, rm0), M1 = fmaxf(m1, rm1);
        const float f0 = __expf(m0 - M0), f1 = __expf(m1 - M1);
        m0 = M0; m1 = M1;
        l0 *= f0; l1 *= f1;
        #pragma unroll
        for (int dt = 0; dt < 16; ++dt) {
            O[dt][0] *= f0; O[dt][1] *= f0;
            O[dt][2] *= f1; O[dt][3] *= f1;
        }

        #pragma unroll
        for (int kc = 0; kc < 4; ++kc) {
            uint32_t pa[4];
            #pragma unroll
            for (int half = 0; half < 2; ++half) {
                const int nt = kc * 2 + half;
                const float p0 = __expf(S[nt][0] - M0);
                const float p1 = __expf(S[nt][1] - M0);
                const float p2 = __expf(S[nt][2] - M1);
                const float p3 = __expf(S[nt][3] - M1);
                l0 += p0 + p1; l1 += p2 + p3;
                pa[half ? 2 : 0] = pkh(__float2half_rn(p0), __float2half_rn(p1));
                pa[half ? 3 : 1] = pkh(__float2half_rn(p2), __float2half_rn(p3));
            }
            #pragma unroll
            for (int dt = 0; dt < 16; dt += 2) {
                uint32_t bv[4];
                const int voff = (kc * 16 + vrow) * 136 + (dt + vsel) * 8;
                ldsm_x4t(bv, cV + voff);
                mma_f16(O[dt],     pa, bv);
                mma_f16(O[dt + 1], pa, bv + 2);
            }
        }
        __syncthreads();
    }

    l0 += __shfl_xor_sync(~0u, l0, 1); l0 += __shfl_xor_sync(~0u, l0, 2);
    l1 += __shfl_xor_sync(~0u, l1, 1); l1 += __shfl_xor_sync(~0u, l1, 2);
    const float i0 = 1.f / l0, i1 = 1.f / l1;
    const long og = ((long)b * LL + q0 + wid * 16) * DD + h * KHD;
    #pragma unroll
    for (int dt = 0; dt < 16; ++dt) {
        const int col = dt * 8 + tc * 2;
        *(uint32_t*)&O_[og + (long)tr * DD + col] =
            pkh(__float2half_rn(O[dt][0] * i0), __float2half_rn(O[dt][1] * i0));
        *(uint32_t*)&O_[og + (long)(tr + 8) * DD + col] =
            pkh(__float2half_rn(O[dt][2] * i1), __float2half_rn(O[dt][3] * i1));
    }
}

// ---------------- converts ----------------
__global__ void split_b(const float* __restrict__ in, bf16* __restrict__ hi,
                        bf16* __restrict__ lo, int n4)
{
    const int i = blockIdx.x * 256 + threadIdx.x;
    if (i >= n4) return;
    const float4 v = ((const float4*)in)[i];
    bf16 h0, l0, h1, l1, h2, l2, h3, l3;
    bsplit(v.x, h0, l0); bsplit(v.y, h1, l1);
    bsplit(v.z, h2, l2); bsplit(v.w, h3, l3);
    ((uint32_t*)hi)[i * 2]     = pkb(h0, h1);
    ((uint32_t*)hi)[i * 2 + 1] = pkb(h2, h3);
    ((uint32_t*)lo)[i * 2]     = pkb(l0, l1);
    ((uint32_t*)lo)[i * 2 + 1] = pkb(l2, l3);
}
__global__ void split_h(const float* __restrict__ in, h16* __restrict__ hi,
                        h16* __restrict__ lo, int n4)
{
    const int i = blockIdx.x * 256 + threadIdx.x;
    if (i >= n4) return;
    const float4 v = ((const float4*)in)[i];
    h16 h0, l0, h1, l1, h2, l2, h3, l3;
    hsplit(v.x, h0, l0); hsplit(v.y, h1, l1);
    hsplit(v.z, h2, l2); hsplit(v.w, h3, l3);
    ((uint32_t*)hi)[i * 2]     = pkh(h0, h1);
    ((uint32_t*)hi)[i * 2 + 1] = pkh(h2, h3);
    if (lo) {
        ((uint32_t*)lo)[i * 2]     = pkh(l0, l1);
        ((uint32_t*)lo)[i * 2 + 1] = pkh(l2, l3);
    }
}

// ---------------- pool init + logits ----------------
__global__ void init_pool(float* __restrict__ psum, unsigned* __restrict__ pmax)
{
    const int i = blockIdx.x * 256 + threadIdx.x;
    if (i < BB * DD) { psum[i] = 0.f; pmax[i] = 0u; }
}

__global__ void logits_kernel(const float* __restrict__ psum,
                              const unsigned* __restrict__ pmax,
                              const float* __restrict__ Wm,
                              const float* __restrict__ bm,
                              float* __restrict__ out)
{
    const int b = blockIdx.x;
    __shared__ float ps[DD];
    for (int i = threadIdx.x; i < DD; i += blockDim.x)
        ps[i] = psum[b * DD + i] * (1.f / LL) + fdec(pmax[b * DD + i]);
    __syncthreads();
    const int o = threadIdx.x;
    if (o < OUTN) {
        float s = bm[o];
        const float* w = Wm + (long)o * DD;
        for (int kk = 0; kk < DD; ++kk) s += ps[kk] * w[kk];
        out[b * OUTN + o] = s;
    }
}

// =================================================================
extern "C" void kernel_launch(void* const* d_in, const int* in_sizes, int n_in,
                              void* d_out, int out_size)
{
    const float* x0   = (const float*)d_in[0];
    const float* x1   = (const float*)d_in[1];
    const float* x2   = (const float*)d_in[2];
    const float* Wk   = (const float*)d_in[5];
    const float* Wq   = (const float*)d_in[6];
    const float* Wv   = (const float*)d_in[7];
    const float* Wu   = (const float*)d_in[8];
    const float* bu   = (const float*)d_in[9];
    const float* Wmlp = (const float*)d_in[10];
    const float* bmlp = (const float*)d_in[11];
    float* out = (float*)d_out;

    bf16 *x1h,*x1l,*x2h,*x2l,*wkh,*wkl,*wqh,*wql,*qh,*ql,*kh,*kl;
    h16  *x0h,*wvh,*wuh,*wul,*vv,*att;
    float *psum; unsigned *pmax;
    cudaGetSymbolAddress((void**)&x1h, g_x1h); cudaGetSymbolAddress((void**)&x1l, g_x1l);
    cudaGetSymbolAddress((void**)&x2h, g_x2h); cudaGetSymbolAddress((void**)&x2l, g_x2l);
    cudaGetSymbolAddress((void**)&wkh, g_wkh); cudaGetSymbolAddress((void**)&wkl, g_wkl);
    cudaGetSymbolAddress((void**)&wqh, g_wqh); cudaGetSymbolAddress((void**)&wql, g_wql);
    cudaGetSymbolAddress((void**)&qh,  g_qh);  cudaGetSymbolAddress((void**)&ql,  g_ql);
    cudaGetSymbolAddress((void**)&kh,  g_kh);  cudaGetSymbolAddress((void**)&kl,  g_kl);
    cudaGetSymbolAddress((void**)&x0h, g_x0h);
    cudaGetSymbolAddress((void**)&wvh, g_wvh);
    cudaGetSymbolAddress((void**)&wuh, g_wuh); cudaGetSymbolAddress((void**)&wul, g_wul);
    cudaGetSymbolAddress((void**)&vv,  g_vv);  cudaGetSymbolAddress((void**)&att, g_att);
    cudaGetSymbolAddress((void**)&psum, g_psum);
    cudaGetSymbolAddress((void**)&pmax, g_pmax);

    const float scale = powf((float)KHD, -0.25f);
    const int M = BB * LL;

    constexpr int SM_B3 = 4 * 4 * 128 * 24 * 2;   // 98304
    constexpr int SM_H2 = 4 * 3 * 128 * 24 * 2;   // 73728
    constexpr int SM_H1 = 4 * 2 * 128 * 24 * 2;   // 49152
    constexpr int SM_FL = 2*128*136*2 + 2*3*64*136*2;  // 174080
    cudaFuncSetAttribute(gemm_b3,     cudaFuncAttributeMaxDynamicSharedMemorySize, SM_B3);
    cudaFuncSetAttribute(gemm_h<1,0>, cudaFuncAttributeMaxDynamicSharedMemorySize, SM_H1);
    cudaFuncSetAttribute(gemm_h<2,1>, cudaFuncAttributeMaxDynamicSharedMemorySize, SM_H2);
    cudaFuncSetAttribute(flash_k,     cudaFuncAttributeMaxDynamicSharedMemorySize, SM_FL);

    // --- converts ---
    {
        const int nx4 = BB * LL * DD / 4, nw4 = DD * DD / 4;
        split_b<<<(nx4 + 255) / 256, 256>>>(x1, x1h, x1l, nx4);
        split_b<<<(nx4 + 255) / 256, 256>>>(x2, x2h, x2l, nx4);
        split_b<<<(nw4 + 255) / 256, 256>>>(Wk, wkh, wkl, nw4);
        split_b<<<(nw4 + 255) / 256, 256>>>(Wq, wqh, wql, nw4);
        split_h<<<(nx4 + 255) / 256, 256>>>(x0, x0h, nullptr, nx4);
        split_h<<<(nw4 + 255) / 256, 256>>>(Wv, wvh, nullptr, nw4);
        split_h<<<(nw4 + 255) / 256, 256>>>(Wu, wuh, wul, nw4);
    }

    dim3 blk(256);
    dim3 gproj(DD / 128, M / 128);

    // --- projections ---
    gemm_b3<<<gproj, blk, SM_B3>>>(x2h, x2l, wkh, wkl, qh, ql, scale);
    gemm_b3<<<gproj, blk, SM_B3>>>(x1h, x1l, wqh, wql, kh, kl, scale);
    gemm_h<1,0><<<gproj, blk, SM_H1>>>(x0h, wvh, nullptr, vv, nullptr, nullptr, nullptr);

    // --- fused attention ---
    {
        dim3 grid(LL / 128, BB * HH);
        flash_k<<<grid, blk, SM_FL>>>(qh, ql, kh, kl, vv, att);
    }

    // --- unify + fused pooling ---
    init_pool<<<(BB * DD + 255) / 256, 256>>>(psum, pmax);
    gemm_h<2,1><<<gproj, blk, SM_H2>>>(att, wuh, wul, nullptr, bu, psum, pmax);

    // --- logits ---
    logits_kernel<<<BB, 256>>>(psum, pmax, Wmlp, bmlp, out);
}

// round 10
// speedup vs baseline: 6.1856x; 1.0890x over previous
#include <cuda_runtime.h>
#include <cuda_bf16.h>
#include <cuda_fp16.h>
#include <math.h>
#include <stdint.h>

#define BB 16
#define LL 1024
#define DD 1024
#define HH 8
#define KHD 128
#define OUTN 64

typedef __nv_bfloat16  bf16;
typedef __nv_bfloat162 bf162;
typedef __half  h16;
typedef __half2 h162;

// ---------------- scratch ----------------
__device__ bf16 g_x1h[BB*LL*DD], g_x1l[BB*LL*DD];
__device__ bf16 g_x2h[BB*LL*DD], g_x2l[BB*LL*DD];
__device__ bf16 g_wkh[DD*DD], g_wkl[DD*DD];
__device__ bf16 g_wqh[DD*DD], g_wql[DD*DD];
__device__ bf16 g_qh[BB*LL*DD], g_ql[BB*LL*DD];
__device__ bf16 g_kh[BB*LL*DD], g_kl[BB*LL*DD];
__device__ h16 g_x0h[BB*LL*DD];
__device__ h16 g_wvh[DD*DD];
__device__ h16 g_wuh[DD*DD];
__device__ h16 g_vv [BB*LL*DD];
__device__ h16 g_att[BB*LL*DD];
__device__ float    g_psum[BB*DD];
__device__ unsigned g_pmax[BB*DD];

// ---------------- helpers ----------------
__device__ __forceinline__ void bsplit(float x, bf16& h, bf16& l) {
    h = __float2bfloat16_rn(x);
    l = __float2bfloat16_rn(x - __bfloat162float(h));
}
__device__ __forceinline__ uint32_t pkb(bf16 x, bf16 y) {
    bf162 t; t.x = x; t.y = y; return *(uint32_t*)&t;
}
__device__ __forceinline__ uint32_t pkh(h16 x, h16 y) {
    h162 t; t.x = x; t.y = y; return *(uint32_t*)&t;
}
__device__ __forceinline__ void cpa16(void* s, const void* g) {
    uint32_t sa = (uint32_t)__cvta_generic_to_shared(s);
    asm volatile("cp.async.cg.shared.global [%0], [%1], 16;" :: "r"(sa), "l"(g));
}
__device__ __forceinline__ void cp_commit() {
    asm volatile("cp.async.commit_group;" ::: "memory");
}
__device__ __forceinline__ void cp_wait1() {
    asm volatile("cp.async.wait_group 1;" ::: "memory");
}
__device__ __forceinline__ void cp_wait2() {
    asm volatile("cp.async.wait_group 2;" ::: "memory");
}
__device__ __forceinline__ void ldsm_x4(uint32_t* r, const void* p) {
    uint32_t a = (uint32_t)__cvta_generic_to_shared(p);
    asm volatile("ldmatrix.sync.aligned.m8n8.x4.shared.b16 {%0,%1,%2,%3}, [%4];"
        : "=r"(r[0]), "=r"(r[1]), "=r"(r[2]), "=r"(r[3]) : "r"(a));
}
__device__ __forceinline__ void ldsm_x4t(uint32_t* r, const void* p) {
    uint32_t a = (uint32_t)__cvta_generic_to_shared(p);
    asm volatile("ldmatrix.sync.aligned.m8n8.x4.trans.shared.b16 {%0,%1,%2,%3}, [%4];"
        : "=r"(r[0]), "=r"(r[1]), "=r"(r[2]), "=r"(r[3]) : "r"(a));
}
__device__ __forceinline__ void mma_bf16(float* c, const uint32_t* a, const uint32_t* b) {
    asm volatile(
        "mma.sync.aligned.m16n8k16.row.col.f32.bf16.bf16.f32 "
        "{%0,%1,%2,%3},{%4,%5,%6,%7},{%8,%9},{%0,%1,%2,%3};"
        : "+f"(c[0]), "+f"(c[1]), "+f"(c[2]), "+f"(c[3])
        : "r"(a[0]), "r"(a[1]), "r"(a[2]), "r"(a[3]), "r"(b[0]), "r"(b[1]));
}
__device__ __forceinline__ void mma_f16(float* c, const uint32_t* a, const uint32_t* b) {
    asm volatile(
        "mma.sync.aligned.m16n8k16.row.col.f32.f16.f16.f32 "
        "{%0,%1,%2,%3},{%4,%5,%6,%7},{%8,%9},{%0,%1,%2,%3};"
        : "+f"(c[0]), "+f"(c[1]), "+f"(c[2]), "+f"(c[3])
        : "r"(a[0]), "r"(a[1]), "r"(a[2]), "r"(a[3]), "r"(b[0]), "r"(b[1]));
}
__device__ __forceinline__ unsigned fkey(float v) {
    unsigned u = __float_as_uint(v);
    return (u & 0x80000000u) ? ~u : (u | 0x80000000u);
}
__device__ __forceinline__ float fdec(unsigned k) {
    unsigned u = (k & 0x80000000u) ? (k ^ 0x80000000u) : ~k;
    return __uint_as_float(u);
}

// =================================================================
// bf16 3-MMA TN GEMM, z-batched over 2 problem sets (q & k proj).
// BM=BN=128, BK=16, 4-stage cp.async, 2 CTA/SM.
// =================================================================
__global__ void __launch_bounds__(256, 2)
gemm_b3(const bf16* __restrict__ A0h, const bf16* __restrict__ A0l,
        const bf16* __restrict__ B0h, const bf16* __restrict__ B0l,
        bf16* __restrict__ C0h, bf16* __restrict__ C0l,
        const bf16* __restrict__ A1h, const bf16* __restrict__ A1l,
        const bf16* __restrict__ B1h, const bf16* __restrict__ B1l,
        bf16* __restrict__ C1h, bf16* __restrict__ C1l,
        float alpha)
{
    extern __shared__ __align__(16) char smem[];
    constexpr int RS  = 24;
    constexpr int ARR = 128 * RS;
    constexpr int STG = 4 * ARR;

    const bf16* Ah = blockIdx.z ? A1h : A0h;
    const bf16* Al = blockIdx.z ? A1l : A0l;
    const bf16* Bh = blockIdx.z ? B1h : B0h;
    const bf16* Bl = blockIdx.z ? B1l : B0l;
    bf16* Ch = blockIdx.z ? C1h : C0h;
    bf16* Cl = blockIdx.z ? C1l : C0l;

    const int bm = blockIdx.y * 128, bn = blockIdx.x * 128;
    const int u = threadIdx.x, wid = u >> 5, lane = u & 31;
    const int wm = (wid >> 2) * 64, wn = (wid & 3) * 32;

    float acc[4][4][4];
    #pragma unroll
    for (int i = 0; i < 4; ++i)
        #pragma unroll
        for (int j = 0; j < 4; ++j)
            #pragma unroll
            for (int p = 0; p < 4; ++p) acc[i][j][p] = 0.f;

    const int srow = u >> 1, shalf = (u & 1) * 8;
    auto stage = [&](int buf, int k0) {
        bf16* s0 = (bf16*)smem + (long)buf * STG + srow * RS + shalf;
        const long ga = (long)(bm + srow) * DD + k0 + shalf;
        const long gb = (long)(bn + srow) * DD + k0 + shalf;
        cpa16(s0,           Ah + ga);
        cpa16(s0 + ARR,     Al + ga);
        cpa16(s0 + 2 * ARR, Bh + gb);
        cpa16(s0 + 3 * ARR, Bl + gb);
    };

    constexpr int nst = DD / 16;
    #pragma unroll
    for (int t = 0; t < 3; ++t) { stage(t, t * 16); cp_commit(); }

    const int arow = lane & 15, asel = (lane >> 4) * 8;
    const int brow = ((lane >> 4) & 1) * 8 + (lane & 7);
    const int bcol = ((lane >> 3) & 1) * 8;

    for (int s = 0; s < nst; ++s) {
        cp_wait2();
        __syncthreads();
        if (s + 3 < nst) stage((s + 3) & 3, (s + 3) * 16);
        cp_commit();

        const bf16* base = (const bf16*)smem + (long)(s & 3) * STG;
        const bf16* sAh = base;
        const bf16* sAl = base + ARR;
        const bf16* sBh = base + 2 * ARR;
        const bf16* sBl = base + 3 * ARR;

        uint32_t ah[4][4], al[4][4];
        #pragma unroll
        for (int mt = 0; mt < 4; ++mt) {
            const int off = (wm + mt * 16 + arow) * RS + asel;
            ldsm_x4(ah[mt], sAh + off);
            ldsm_x4(al[mt], sAl + off);
        }
        #pragma unroll
        for (int np = 0; np < 2; ++np) {
            uint32_t bh4[4], bl4[4];
            const int off = (wn + np * 16 + brow) * RS + bcol;
            ldsm_x4(bh4, sBh + off);
            ldsm_x4(bl4, sBl + off);
            #pragma unroll
            for (int half = 0; half < 2; ++half) {
                const int nt = np * 2 + half;
                #pragma unroll
                for (int mt = 0; mt < 4; ++mt) {
                    mma_bf16(acc[mt][nt], ah[mt], bh4 + half * 2);
                    mma_bf16(acc[mt][nt], ah[mt], bl4 + half * 2);
                    mma_bf16(acc[mt][nt], al[mt], bh4 + half * 2);
                }
            }
        }
    }

    const int tr = lane >> 2, tc = lane & 3;
    #pragma unroll
    for (int mt = 0; mt < 4; ++mt) {
        const int row = bm + wm + mt * 16 + tr;
        #pragma unroll
        for (int nt = 0; nt < 4; ++nt) {
            const int col = bn + wn + nt * 8 + tc * 2;
            const float* c = acc[mt][nt];
            bf16 h0, l0, h1, l1;
            bsplit(c[0] * alpha, h0, l0); bsplit(c[1] * alpha, h1, l1);
            *(uint32_t*)&Ch[(long)row * DD + col] = pkb(h0, h1);
            *(uint32_t*)&Cl[(long)row * DD + col] = pkb(l0, l1);
            bsplit(c[2] * alpha, h0, l0); bsplit(c[3] * alpha, h1, l1);
            *(uint32_t*)&Ch[(long)(row + 8) * DD + col] = pkb(h0, h1);
            *(uint32_t*)&Cl[(long)(row + 8) * DD + col] = pkb(l0, l1);
        }
    }
}

// =================================================================
// fp16 1-MMA TN GEMM. POOL 0: fp16 C;  POOL 1: fused mean/max pool.
// =================================================================
template<int POOL>
__global__ void __launch_bounds__(256, 2)
gemm_h1(const h16* __restrict__ Ax, const h16* __restrict__ Bh,
        h16* __restrict__ Chf, const float* __restrict__ bias,
        float* __restrict__ psum, unsigned* __restrict__ pmax)
{
    extern __shared__ __align__(16) char smem[];
    constexpr int RS  = 24;
    constexpr int ARR = 128 * RS;
    constexpr int STG = 2 * ARR;

    const int bm = blockIdx.y * 128, bn = blockIdx.x * 128;
    const int u = threadIdx.x, wid = u >> 5, lane = u & 31;
    const int wm = (wid >> 2) * 64, wn = (wid & 3) * 32;

    float acc[4][4][4];
    #pragma unroll
    for (int i = 0; i < 4; ++i)
        #pragma unroll
        for (int j = 0; j < 4; ++j)
            #pragma unroll
            for (int p = 0; p < 4; ++p) acc[i][j][p] = 0.f;

    const int srow = u >> 1, shalf = (u & 1) * 8;
    auto stage = [&](int buf, int k0) {
        h16* s0 = (h16*)smem + (long)buf * STG + srow * RS + shalf;
        cpa16(s0,       Ax + (long)(bm + srow) * DD + k0 + shalf);
        cpa16(s0 + ARR, Bh + (long)(bn + srow) * DD + k0 + shalf);
    };

    constexpr int nst = DD / 16;
    #pragma unroll
    for (int t = 0; t < 3; ++t) { stage(t, t * 16); cp_commit(); }

    const int arow = lane & 15, asel = (lane >> 4) * 8;
    const int brow = ((lane >> 4) & 1) * 8 + (lane & 7);
    const int bcol = ((lane >> 3) & 1) * 8;

    for (int s = 0; s < nst; ++s) {
        cp_wait2();
        __syncthreads();
        if (s + 3 < nst) stage((s + 3) & 3, (s + 3) * 16);
        cp_commit();

        const h16* base = (const h16*)smem + (long)(s & 3) * STG;
        const h16* sA  = base;
        const h16* sBh = base + ARR;

        uint32_t ah[4][4];
        #pragma unroll
        for (int mt = 0; mt < 4; ++mt)
            ldsm_x4(ah[mt], sA + (wm + mt * 16 + arow) * RS + asel);
        #pragma unroll
        for (int np = 0; np < 2; ++np) {
            uint32_t bh4[4];
            ldsm_x4(bh4, sBh + (wn + np * 16 + brow) * RS + bcol);
            #pragma unroll
            for (int half = 0; half < 2; ++half) {
                const int nt = np * 2 + half;
                #pragma unroll
                for (int mt = 0; mt < 4; ++mt)
                    mma_f16(acc[mt][nt], ah[mt], bh4 + half * 2);
            }
        }
    }

    const int tr = lane >> 2, tc = lane & 3;
    if (POOL == 0) {
        #pragma unroll
        for (int mt = 0; mt < 4; ++mt) {
            const int row = bm + wm + mt * 16 + tr;
            #pragma unroll
            for (int nt = 0; nt < 4; ++nt) {
                const int col = bn + wn + nt * 8 + tc * 2;
                const float* c = acc[mt][nt];
                *(uint32_t*)&Chf[(long)row * DD + col] =
                    pkh(__float2half_rn(c[0]), __float2half_rn(c[1]));
                *(uint32_t*)&Chf[(long)(row + 8) * DD + col] =
                    pkh(__float2half_rn(c[2]), __float2half_rn(c[3]));
            }
        }
    } else {
        const int b = bm >> 10;
        float sum[4][2], mx[4][2];
        #pragma unroll
        for (int nt = 0; nt < 4; ++nt) {
            #pragma unroll
            for (int j = 0; j < 2; ++j) {
                const int col = bn + wn + nt * 8 + tc * 2 + j;
                const float bv = __ldg(bias + col);
                float s_ = 0.f, m_ = -1e30f;
                #pragma unroll
                for (int mt = 0; mt < 4; ++mt) {
                    const float v0 = acc[mt][nt][j] + bv;
                    const float v1 = acc[mt][nt][j + 2] + bv;
                    s_ += v0 + v1;
                    m_ = fmaxf(m_, fmaxf(v0, v1));
                }
                sum[nt][j] = s_; mx[nt][j] = m_;
            }
        }
        #pragma unroll
        for (int o = 4; o <= 16; o <<= 1) {
            #pragma unroll
            for (int nt = 0; nt < 4; ++nt)
                #pragma unroll
                for (int j = 0; j < 2; ++j) {
                    sum[nt][j] += __shfl_xor_sync(~0u, sum[nt][j], o);
                    mx[nt][j] = fmaxf(mx[nt][j], __shfl_xor_sync(~0u, mx[nt][j], o));
                }
        }
        if (tr == 0) {
            #pragma unroll
            for (int nt = 0; nt < 4; ++nt)
                #pragma unroll
                for (int j = 0; j < 2; ++j) {
                    const int col = bn + wn + nt * 8 + tc * 2 + j;
                    atomicAdd(&psum[b * DD + col], sum[nt][j]);
                    atomicMax(&pmax[b * DD + col], fkey(mx[nt][j]));
                }
        }
    }
}

// =================================================================
// Fused flash attention (unchanged).
// =================================================================
__global__ void __launch_bounds__(256)
flash_k(const bf16* __restrict__ Qh, const bf16* __restrict__ Ql,
        const bf16* __restrict__ Kh, const bf16* __restrict__ Kl,
        const h16* __restrict__ V, h16* __restrict__ O_)
{
    extern __shared__ __align__(16) char sm[];
    constexpr int QS = 128 * 136;
    constexpr int TS = 64 * 136;
    bf16* sQh = (bf16*)sm;
    bf16* sQl = sQh + QS;
    char* sT  = (char*)(sQl + QS);
    constexpr long STG = 3L * TS * 2;

    const int bh = blockIdx.y, b = bh >> 3, h = bh & 7;
    const int q0 = blockIdx.x * 128;
    const int u = threadIdx.x, wid = u >> 5, lane = u & 31;
    const int tr = lane >> 2, tc = lane & 3;

    const long qg = ((long)b * LL + q0) * DD + h * KHD;
    const long kg = (long)b * LL * DD + h * KHD;

    for (int c = u; c < 2048; c += 256) {
        const int r = c >> 4, s = (c & 15) * 8;
        cpa16(sQh + r * 136 + s, Qh + qg + (long)r * DD + s);
        cpa16(sQl + r * 136 + s, Ql + qg + (long)r * DD + s);
    }
    auto stage = [&](int buf, int kv0) {
        bf16* pKh = (bf16*)(sT + buf * STG);
        bf16* pKl = pKh + TS;
        h16*  pV  = (h16*)(pKl + TS);
        for (int c = u; c < 1024; c += 256) {
            const int r = c >> 4, s = (c & 15) * 8;
            const long g = kg + (long)(kv0 + r) * DD + s;
            cpa16(pKh + r * 136 + s, Kh + g);
            cpa16(pKl + r * 136 + s, Kl + g);
            cpa16(pV  + r * 136 + s, V + g);
        }
    };
    stage(0, 0);
    cp_commit();

    float O[16][4];
    #pragma unroll
    for (int i = 0; i < 16; ++i)
        #pragma unroll
        for (int j = 0; j < 4; ++j) O[i][j] = 0.f;
    float m0 = -1e30f, m1 = -1e30f, l0 = 0.f, l1 = 0.f;

    const int brow = ((lane >> 4) & 1) * 8 + (lane & 7);
    const int bcol = ((lane >> 3) & 1) * 8;
    const int vrow = ((lane >> 3) & 1) * 8 + (lane & 7);
    const int vsel = (lane >> 4);

    for (int t = 0; t < 16; ++t) {
        if (t + 1 < 16) stage((t + 1) & 1, (t + 1) * 64);
        cp_commit();
        cp_wait1();
        __syncthreads();

        const bf16* cKh = (const bf16*)(sT + (t & 1) * STG);
        const bf16* cKl = cKh + TS;
        const h16*  cV  = (const h16*)(cKl + TS);

        float S[8][4];
        #pragma unroll
        for (int i = 0; i < 8; ++i)
            #pragma unroll
            for (int j = 0; j < 4; ++j) S[i][j] = 0.f;

        #pragma unroll
        for (int kk = 0; kk < 128; kk += 16) {
            uint32_t ah[4], al[4];
            const int aoff = (wid * 16 + (lane & 15)) * 136 + kk + (lane >> 4) * 8;
            ldsm_x4(ah, sQh + aoff);
            ldsm_x4(al, sQl + aoff);
            #pragma unroll
            for (int np = 0; np < 4; ++np) {
                uint32_t bh4[4], bl4[4];
                const int boff = (np * 16 + brow) * 136 + kk + bcol;
                ldsm_x4(bh4, cKh + boff);
                ldsm_x4(bl4, cKl + boff);
                #pragma unroll
                for (int half = 0; half < 2; ++half) {
                    float* s_ = S[np * 2 + half];
                    mma_bf16(s_, ah, bh4 + half * 2);
                    mma_bf16(s_, ah, bl4 + half * 2);
                    mma_bf16(s_, al, bh4 + half * 2);
                }
            }
        }

        float rm0 = -1e30f, rm1 = -1e30f;
        #pragma unroll
        for (int nt = 0; nt < 8; ++nt) {
            rm0 = fmaxf(rm0, fmaxf(S[nt][0], S[nt][1]));
            rm1 = fmaxf(rm1, fmaxf(S[nt][2], S[nt][3]));
        }
        rm0 = fmaxf(rm0, __shfl_xor_sync(~0u, rm0, 1));
        rm0 = fmaxf(rm0, __shfl_xor_sync(~0u, rm0, 2));
        rm1 = fmaxf(rm1, __shfl_xor_sync(~0u, rm1, 1));
        rm1 = fmaxf(rm1, __shfl_xor_sync(~0u, rm1, 2));
        const float M0 = fmaxf(m0, rm0), M1 = fmaxf(m1, rm1);
        const float f0 = __expf(m0 - M0), f1 = __expf(m1 - M1);
        m0 = M0; m1 = M1;
        l0 *= f0; l1 *= f1;
        #pragma unroll
        for (int dt = 0; dt < 16; ++dt) {
            O[dt][0] *= f0; O[dt][1] *= f0;
            O[dt][2] *= f1; O[dt][3] *= f1;
        }

        #pragma unroll
        for (int kc = 0; kc < 4; ++kc) {
            uint32_t pa[4];
            #pragma unroll
            for (int half = 0; half < 2; ++half) {
                const int nt = kc * 2 + half;
                const float p0 = __expf(S[nt][0] - M0);
                const float p1 = __expf(S[nt][1] - M0);
                const float p2 = __expf(S[nt][2] - M1);
                const float p3 = __expf(S[nt][3] - M1);
                l0 += p0 + p1; l1 += p2 + p3;
                pa[half ? 2 : 0] = pkh(__float2half_rn(p0), __float2half_rn(p1));
                pa[half ? 3 : 1] = pkh(__float2half_rn(p2), __float2half_rn(p3));
            }
            #pragma unroll
            for (int dt = 0; dt < 16; dt += 2) {
                uint32_t bv[4];
                const int voff = (kc * 16 + vrow) * 136 + (dt + vsel) * 8;
                ldsm_x4t(bv, cV + voff);
                mma_f16(O[dt],     pa, bv);
                mma_f16(O[dt + 1], pa, bv + 2);
            }
        }
        __syncthreads();
    }

    l0 += __shfl_xor_sync(~0u, l0, 1); l0 += __shfl_xor_sync(~0u, l0, 2);
    l1 += __shfl_xor_sync(~0u, l1, 1); l1 += __shfl_xor_sync(~0u, l1, 2);
    const float i0 = 1.f / l0, i1 = 1.f / l1;
    const long og = ((long)b * LL + q0 + wid * 16) * DD + h * KHD;
    #pragma unroll
    for (int dt = 0; dt < 16; ++dt) {
        const int col = dt * 8 + tc * 2;
        *(uint32_t*)&O_[og + (long)tr * DD + col] =
            pkh(__float2half_rn(O[dt][0] * i0), __float2half_rn(O[dt][1] * i0));
        *(uint32_t*)&O_[og + (long)(tr + 8) * DD + col] =
            pkh(__float2half_rn(O[dt][2] * i1), __float2half_rn(O[dt][3] * i1));
    }
}

// ---------------- fused converts ----------------
__device__ __forceinline__ void split4_b(const float* in, bf16* hi, bf16* lo, int i)
{
    const float4 v = ((const float4*)in)[i];
    bf16 h0, l0, h1, l1, h2, l2, h3, l3;
    bsplit(v.x, h0, l0); bsplit(v.y, h1, l1);
    bsplit(v.z, h2, l2); bsplit(v.w, h3, l3);
    ((uint32_t*)hi)[i * 2]     = pkb(h0, h1);
    ((uint32_t*)hi)[i * 2 + 1] = pkb(h2, h3);
    ((uint32_t*)lo)[i * 2]     = pkb(l0, l1);
    ((uint32_t*)lo)[i * 2 + 1] = pkb(l2, l3);
}
__device__ __forceinline__ void conv4_h(const float* in, h16* hi, int i)
{
    const float4 v = ((const float4*)in)[i];
    ((uint32_t*)hi)[i * 2]     = pkh(__float2half_rn(v.x), __float2half_rn(v.y));
    ((uint32_t*)hi)[i * 2 + 1] = pkh(__float2half_rn(v.z), __float2half_rn(v.w));
}

__global__ void conv_x(const float* __restrict__ x1, bf16* __restrict__ x1h, bf16* __restrict__ x1l,
                       const float* __restrict__ x2, bf16* __restrict__ x2h, bf16* __restrict__ x2l,
                       const float* __restrict__ x0, h16* __restrict__ x0h)
{
    const int i = blockIdx.x * 256 + threadIdx.x;   // < 4194304
    switch (blockIdx.y) {
        case 0: split4_b(x1, x1h, x1l, i); break;
        case 1: split4_b(x2, x2h, x2l, i); break;
        default: conv4_h(x0, x0h, i); break;
    }
}
__global__ void conv_w(const float* __restrict__ Wk, bf16* __restrict__ wkh, bf16* __restrict__ wkl,
                       const float* __restrict__ Wq, bf16* __restrict__ wqh, bf16* __restrict__ wql,
                       const float* __restrict__ Wv, h16* __restrict__ wvh,
                       const float* __restrict__ Wu, h16* __restrict__ wuh)
{
    const int i = blockIdx.x * 256 + threadIdx.x;   // < 262144
    switch (blockIdx.y) {
        case 0: split4_b(Wk, wkh, wkl, i); break;
        case 1: split4_b(Wq, wqh, wql, i); break;
        case 2: conv4_h(Wv, wvh, i); break;
        default: conv4_h(Wu, wuh, i); break;
    }
}

// ---------------- pool init + logits ----------------
__global__ void init_pool(float* __restrict__ psum, unsigned* __restrict__ pmax)
{
    const int i = blockIdx.x * 256 + threadIdx.x;
    if (i < BB * DD) { psum[i] = 0.f; pmax[i] = 0u; }
}

__global__ void logits_kernel(const float* __restrict__ psum,
                              const unsigned* __restrict__ pmax,
                              const float* __restrict__ Wm,
                              const float* __restrict__ bm,
                              float* __restrict__ out)
{
    const int b = blockIdx.x;
    __shared__ float ps[DD];
    __shared__ float red[4][OUTN];
    for (int i = threadIdx.x; i < DD; i += 256)
        ps[i] = psum[b * DD + i] * (1.f / LL) + fdec(pmax[b * DD + i]);
    __syncthreads();
    const int o = threadIdx.x & 63, part = threadIdx.x >> 6;
    float s = 0.f;
    const float* w = Wm + (long)o * DD + part * 256;
    const float* p = ps + part * 256;
    #pragma unroll 8
    for (int kk = 0; kk < 256; ++kk) s += p[kk] * w[kk];
    red[part][o] = s;
    __syncthreads();
    if (part == 0)
        out[b * OUTN + o] = red[0][o] + red[1][o] + red[2][o] + red[3][o] + bm[o];
}

// =================================================================
extern "C" void kernel_launch(void* const* d_in, const int* in_sizes, int n_in,
                              void* d_out, int out_size)
{
    const float* x0   = (const float*)d_in[0];
    const float* x1   = (const float*)d_in[1];
    const float* x2   = (const float*)d_in[2];
    const float* Wk   = (const float*)d_in[5];
    const float* Wq   = (const float*)d_in[6];
    const float* Wv   = (const float*)d_in[7];
    const float* Wu   = (const float*)d_in[8];
    const float* bu   = (const float*)d_in[9];
    const float* Wmlp = (const float*)d_in[10];
    const float* bmlp = (const float*)d_in[11];
    float* out = (float*)d_out;

    bf16 *x1h,*x1l,*x2h,*x2l,*wkh,*wkl,*wqh,*wql,*qh,*ql,*kh,*kl;
    h16  *x0h,*wvh,*wuh,*vv,*att;
    float *psum; unsigned *pmax;
    cudaGetSymbolAddress((void**)&x1h, g_x1h); cudaGetSymbolAddress((void**)&x1l, g_x1l);
    cudaGetSymbolAddress((void**)&x2h, g_x2h); cudaGetSymbolAddress((void**)&x2l, g_x2l);
    cudaGetSymbolAddress((void**)&wkh, g_wkh); cudaGetSymbolAddress((void**)&wkl, g_wkl);
    cudaGetSymbolAddress((void**)&wqh, g_wqh); cudaGetSymbolAddress((void**)&wql, g_wql);
    cudaGetSymbolAddress((void**)&qh,  g_qh);  cudaGetSymbolAddress((void**)&ql,  g_ql);
    cudaGetSymbolAddress((void**)&kh,  g_kh);  cudaGetSymbolAddress((void**)&kl,  g_kl);
    cudaGetSymbolAddress((void**)&x0h, g_x0h);
    cudaGetSymbolAddress((void**)&wvh, g_wvh);
    cudaGetSymbolAddress((void**)&wuh, g_wuh);
    cudaGetSymbolAddress((void**)&vv,  g_vv);  cudaGetSymbolAddress((void**)&att, g_att);
    cudaGetSymbolAddress((void**)&psum, g_psum);
    cudaGetSymbolAddress((void**)&pmax, g_pmax);

    const float scale = powf((float)KHD, -0.25f);
    const int M = BB * LL;

    constexpr int SM_B3 = 4 * 4 * 128 * 24 * 2;   // 98304
    constexpr int SM_H1 = 4 * 2 * 128 * 24 * 2;   // 49152
    constexpr int SM_FL = 2*128*136*2 + 2*3*64*136*2;  // 174080
    cudaFuncSetAttribute(gemm_b3,    cudaFuncAttributeMaxDynamicSharedMemorySize, SM_B3);
    cudaFuncSetAttribute(gemm_h1<0>, cudaFuncAttributeMaxDynamicSharedMemorySize, SM_H1);
    cudaFuncSetAttribute(gemm_h1<1>, cudaFuncAttributeMaxDynamicSharedMemorySize, SM_H1);
    cudaFuncSetAttribute(flash_k,    cudaFuncAttributeMaxDynamicSharedMemorySize, SM_FL);

    // --- converts (2 launches) ---
    {
        dim3 gx(BB * LL * DD / 4 / 256, 3);
        conv_x<<<gx, 256>>>(x1, x1h, x1l, x2, x2h, x2l, x0, x0h);
        dim3 gw(DD * DD / 4 / 256, 4);
        conv_w<<<gw, 256>>>(Wk, wkh, wkl, Wq, wqh, wql, Wv, wvh, Wu, wuh);
    }
    init_pool<<<(BB * DD + 255) / 256, 256>>>(psum, pmax);

    dim3 blk(256);

    // --- q & k projections (one z=2 launch) + v ---
    {
        dim3 g2(DD / 128, M / 128, 2);
        gemm_b3<<<g2, blk, SM_B3>>>(x2h, x2l, wkh, wkl, qh, ql,
                                    x1h, x1l, wqh, wql, kh, kl, scale);
        dim3 g1(DD / 128, M / 128);
        gemm_h1<0><<<g1, blk, SM_H1>>>(x0h, wvh, vv, nullptr, nullptr, nullptr);
    }

    // --- fused attention ---
    {
        dim3 grid(LL / 128, BB * HH);
        flash_k<<<grid, blk, SM_FL>>>(qh, ql, kh, kl, vv, att);
    }

    // --- unify (1-MMA) + fused pooling ---
    {
        dim3 g1(DD / 128, M / 128);
        gemm_h1<1><<<g1, blk, SM_H1>>>(att, wuh, nullptr, bu, psum, pmax);
    }

    // --- logits ---
    logits_kernel<<<BB, 256>>>(psum, pmax, Wmlp, bmlp, out);
}